// round 4
// baseline (speedup 1.0000x reference)
#include <cuda_runtime.h>
#include <math.h>

#define B_  2
#define L_  2048
#define D_  2048
#define NH_ 16
#define NKV_ 8
#define HD_ 128
#define GQ_ 2
#define SCALE_ 0.08838834764831845f  // 128^-0.5

// Scratch (static device globals — no allocation allowed)
__device__ float g_q[(size_t)B_ * L_ * NH_ * HD_];
__device__ float g_k[(size_t)B_ * L_ * NKV_ * HD_];
__device__ float g_v[(size_t)B_ * L_ * NKV_ * HD_];
__device__ float g_o[(size_t)B_ * L_ * NH_ * HD_];
__device__ float g_cos[(size_t)L_ * 64];
__device__ float g_sin[(size_t)L_ * 64];

// ---------------------------------------------------------------------------
// SGEMM: C[M,N] = A[M,K] @ B[N,K]^T   (A,B,C row-major)
// ---------------------------------------------------------------------------
__global__ void __launch_bounds__(256) sgemm_nt(const float* __restrict__ A,
                                                const float* __restrict__ Bm,
                                                float* __restrict__ C,
                                                int M, int N, int K) {
    __shared__ float As[16][132];
    __shared__ float Bs[16][132];

    const int tid = threadIdx.x;
    const int tx = tid & 15;
    const int ty = tid >> 4;
    const int m0 = blockIdx.y * 128;
    const int n0 = blockIdx.x * 128;

    const int lr = tid >> 2;
    const int lc = (tid & 3) << 2;

    float acc[8][8];
#pragma unroll
    for (int i = 0; i < 8; ++i)
#pragma unroll
        for (int j = 0; j < 8; ++j) acc[i][j] = 0.f;

    for (int k0 = 0; k0 < K; k0 += 16) {
#pragma unroll
        for (int rr = 0; rr < 2; ++rr) {
            const int r = lr + rr * 64;
            float4 a = *(const float4*)(A + (size_t)(m0 + r) * K + k0 + lc);
            As[lc + 0][r] = a.x; As[lc + 1][r] = a.y;
            As[lc + 2][r] = a.z; As[lc + 3][r] = a.w;
            float4 b = *(const float4*)(Bm + (size_t)(n0 + r) * K + k0 + lc);
            Bs[lc + 0][r] = b.x; Bs[lc + 1][r] = b.y;
            Bs[lc + 2][r] = b.z; Bs[lc + 3][r] = b.w;
        }
        __syncthreads();

#pragma unroll
        for (int kk = 0; kk < 16; ++kk) {
            float ar[8], br[8];
            *(float4*)(ar)     = *(const float4*)&As[kk][ty * 8];
            *(float4*)(ar + 4) = *(const float4*)&As[kk][ty * 8 + 4];
            *(float4*)(br)     = *(const float4*)&Bs[kk][tx * 8];
            *(float4*)(br + 4) = *(const float4*)&Bs[kk][tx * 8 + 4];
#pragma unroll
            for (int i = 0; i < 8; ++i)
#pragma unroll
                for (int j = 0; j < 8; ++j) acc[i][j] += ar[i] * br[j];
        }
        __syncthreads();
    }

#pragma unroll
    for (int i = 0; i < 8; ++i) {
        float* cp = C + (size_t)(m0 + ty * 8 + i) * N + n0 + tx * 8;
        *(float4*)(cp)     = make_float4(acc[i][0], acc[i][1], acc[i][2], acc[i][3]);
        *(float4*)(cp + 4) = make_float4(acc[i][4], acc[i][5], acc[i][6], acc[i][7]);
    }
}

// ---------------------------------------------------------------------------
// RoPE table + apply
// ---------------------------------------------------------------------------
__global__ void rope_table_kernel() {
    const int idx = blockIdx.x * blockDim.x + threadIdx.x;
    if (idx >= L_ * 64) return;
    const int i = idx & 63;
    const int pos = idx >> 6;
    const double inv = exp(-(double)i / 64.0 * log(10000.0));
    double sd, cd;
    sincos((double)pos * inv, &sd, &cd);
    g_cos[idx] = (float)cd;
    g_sin[idx] = (float)sd;
}

__global__ void rope_apply_kernel(float* __restrict__ q, float* __restrict__ k) {
    const long long idx = (long long)blockIdx.x * blockDim.x + threadIdx.x;
    const long long total = (long long)B_ * L_ * (NH_ + NKV_) * 64;
    if (idx >= total) return;

    const int i  = (int)(idx & 63);
    long long r  = idx >> 6;
    const int hh = (int)(r % (NH_ + NKV_));
    r /= (NH_ + NKV_);
    const int bl  = (int)r;
    const int pos = bl & (L_ - 1);

    float* ptr;
    if (hh < NH_) ptr = q + ((size_t)bl * NH_ + hh) * HD_;
    else          ptr = k + ((size_t)bl * NKV_ + (hh - NH_)) * HD_;

    const float c = g_cos[pos * 64 + i];
    const float s = g_sin[pos * 64 + i];
    const float a = ptr[i];
    const float b = ptr[i + 64];
    ptr[i]      = a * c - b * s;
    ptr[i + 64] = b * c + a * s;
}

// ---------------------------------------------------------------------------
// Flash attention v3: fused double-sgemm, software-pipelined double buffers,
// 2 CTAs/SM (launch_bounds), one sync per 16-deep slice.
// smem (dynamic, floats):
//   St   [64*132]      S^T / P^T
//   Qs   2 x [16*132]  Q^T d-slices (double buffered)
//   Ks   2 x [16*68]   K^T d-slices
//   Vs   2 x [16*132]  V c-slices
//   stats 3 x 128
// ---------------------------------------------------------------------------
#define ST_SZ   (64 * 132)
#define QS_SZ   (16 * 132)
#define KS_SZ   (16 * 68)
#define VS_SZ   (16 * 132)
#define F3_FLOATS (ST_SZ + 2 * QS_SZ + 2 * KS_SZ + 2 * VS_SZ + 3 * 128)
#define F3_SMEM  (F3_FLOATS * 4)

__global__ void __launch_bounds__(256, 2) flash_attn3(const float* __restrict__ Q,
                                                      const float* __restrict__ K,
                                                      const float* __restrict__ V,
                                                      float* __restrict__ O) {
    extern __shared__ float sm[];
    float* St    = sm;
    float* Qsb   = St + ST_SZ;           // 2 buffers
    float* Ksb   = Qsb + 2 * QS_SZ;
    float* Vsb   = Ksb + 2 * KS_SZ;
    float* row_m = Vsb + 2 * VS_SZ;
    float* row_l = row_m + 128;
    float* row_a = row_l + 128;

    const int tid = threadIdx.x;
    const int b = blockIdx.z, h = blockIdx.y;
    const int kvh = h >> 1;
    const int qt = (gridDim.x - 1) - blockIdx.x;   // heavy tiles first
    const int q0 = qt * 128;

    // staging ids
    const int lr = tid >> 2;             // 0..63
    const int lc = (tid & 3) << 2;       // 0,4,8,12
    const int vrow = tid >> 5;           // 0..7
    const int vcol = (tid & 31) << 2;    // 0..124

    // S-phase compute ids
    const int cb = (tid >> 4) << 2;      // 0..60
    const int rb = (tid & 15) << 3;      // 0..120
    // PV-phase ids
    const int prb = (tid >> 4) << 3;
    const int pdb = (tid & 15) << 3;

    const float* Qg = Q + ((size_t)(b * L_ + q0) * NH_ + h) * HD_;
    const float* Kg = K + ((size_t)(b * L_) * NKV_ + kvh) * HD_;
    const float* Vg = V + ((size_t)(b * L_) * NKV_ + kvh) * HD_;

    if (tid < 128) { row_m[tid] = -1e30f; row_l[tid] = 0.f; }

    float acc_o[8][8];
#pragma unroll
    for (int i = 0; i < 8; ++i)
#pragma unroll
        for (int j = 0; j < 8; ++j) acc_o[i][j] = 0.f;

    __syncthreads();

    const int tmax = 2 * qt + 2;
    for (int t = 0; t < tmax; ++t) {
        const int k0 = t * 64;

        // ---------------- Phase 1: S^T = K @ Q^T (pipelined) ----------------
        float acc_s[4][8];
#pragma unroll
        for (int j = 0; j < 4; ++j)
#pragma unroll
            for (int i = 0; i < 8; ++i) acc_s[j][i] = 0.f;

        float4 kp  = *(const float4*)(Kg + (size_t)(k0 + lr) * (NKV_ * HD_) + lc);
        float4 qp0 = *(const float4*)(Qg + (size_t)lr        * (NH_ * HD_) + lc);
        float4 qp1 = *(const float4*)(Qg + (size_t)(lr + 64) * (NH_ * HD_) + lc);

#pragma unroll
        for (int s = 0; s < 8; ++s) {
            float* Ks = Ksb + (s & 1) * KS_SZ;
            float* Qs = Qsb + (s & 1) * QS_SZ;
            Ks[(lc + 0) * 68 + lr] = kp.x;  Ks[(lc + 1) * 68 + lr] = kp.y;
            Ks[(lc + 2) * 68 + lr] = kp.z;  Ks[(lc + 3) * 68 + lr] = kp.w;
            Qs[(lc + 0) * 132 + lr] = qp0.x;  Qs[(lc + 1) * 132 + lr] = qp0.y;
            Qs[(lc + 2) * 132 + lr] = qp0.z;  Qs[(lc + 3) * 132 + lr] = qp0.w;
            Qs[(lc + 0) * 132 + lr + 64] = qp1.x;  Qs[(lc + 1) * 132 + lr + 64] = qp1.y;
            Qs[(lc + 2) * 132 + lr + 64] = qp1.z;  Qs[(lc + 3) * 132 + lr + 64] = qp1.w;

            if (s < 7) {
                const int dn = (s + 1) * 16;
                kp  = *(const float4*)(Kg + (size_t)(k0 + lr) * (NKV_ * HD_) + dn + lc);
                qp0 = *(const float4*)(Qg + (size_t)lr        * (NH_ * HD_) + dn + lc);
                qp1 = *(const float4*)(Qg + (size_t)(lr + 64) * (NH_ * HD_) + dn + lc);
            }
            __syncthreads();

#pragma unroll
            for (int kk = 0; kk < 16; ++kk) {
                float kr[4], qr[8];
                *(float4*)(kr)     = *(const float4*)&Ks[kk * 68 + cb];
                *(float4*)(qr)     = *(const float4*)&Qs[kk * 132 + rb];
                *(float4*)(qr + 4) = *(const float4*)&Qs[kk * 132 + rb + 4];
#pragma unroll
                for (int j = 0; j < 4; ++j)
#pragma unroll
                    for (int i = 0; i < 8; ++i) acc_s[j][i] += kr[j] * qr[i];
            }
        }

        // store scaled + masked S^T (own cells; readers gated by syncs above)
#pragma unroll
        for (int j = 0; j < 4; ++j) {
            const int thr = (k0 + cb + j) - (q0 + rb);   // valid iff i >= thr
#pragma unroll
            for (int ih = 0; ih < 2; ++ih) {
                float4 o;
                o.x = (ih * 4 + 0 >= thr) ? acc_s[j][ih * 4 + 0] * SCALE_ : -1e30f;
                o.y = (ih * 4 + 1 >= thr) ? acc_s[j][ih * 4 + 1] * SCALE_ : -1e30f;
                o.z = (ih * 4 + 2 >= thr) ? acc_s[j][ih * 4 + 2] * SCALE_ : -1e30f;
                o.w = (ih * 4 + 3 >= thr) ? acc_s[j][ih * 4 + 3] * SCALE_ : -1e30f;
                *(float4*)&St[(cb + j) * 132 + rb + ih * 4] = o;
            }
        }
        __syncthreads();

        // ---------------- Phase 2: online softmax (per q-row) ----------------
        {
            const int r = tid >> 1, sub = tid & 1;
            float* colp = St + r + (sub << 5) * 132;
            float mx = -1e30f;
#pragma unroll 8
            for (int c = 0; c < 32; ++c) mx = fmaxf(mx, colp[c * 132]);
            mx = fmaxf(mx, __shfl_xor_sync(0xffffffffu, mx, 1));
            const float oldm = row_m[r];
            const float nm = fmaxf(mx, oldm);
            float sum = 0.f;
#pragma unroll 8
            for (int c = 0; c < 32; ++c) {
                const float p = __expf(colp[c * 132] - nm);
                colp[c * 132] = p;
                sum += p;
            }
            sum += __shfl_xor_sync(0xffffffffu, sum, 1);
            if (sub == 0) {
                const float al = __expf(oldm - nm);
                row_a[r] = al;
                row_l[r] = row_l[r] * al + sum;
                row_m[r] = nm;
            }
        }
        __syncthreads();

        // ---------------- Phase 3: O = alpha*O + P^T @ V (pipelined) --------
#pragma unroll
        for (int i = 0; i < 8; ++i) {
            const float al = row_a[prb + i];
#pragma unroll
            for (int j = 0; j < 8; ++j) acc_o[i][j] *= al;
        }

        float4 vp0 = *(const float4*)(Vg + (size_t)(k0 + vrow)     * (NKV_ * HD_) + vcol);
        float4 vp1 = *(const float4*)(Vg + (size_t)(k0 + vrow + 8) * (NKV_ * HD_) + vcol);

#pragma unroll
        for (int ch = 0; ch < 4; ++ch) {
            const int c0 = ch * 16;
            float* Vs = Vsb + (ch & 1) * VS_SZ;
            *(float4*)&Vs[vrow * 132 + vcol]       = vp0;
            *(float4*)&Vs[(vrow + 8) * 132 + vcol] = vp1;

            if (ch < 3) {
                vp0 = *(const float4*)(Vg + (size_t)(k0 + c0 + 16 + vrow)     * (NKV_ * HD_) + vcol);
                vp1 = *(const float4*)(Vg + (size_t)(k0 + c0 + 16 + vrow + 8) * (NKV_ * HD_) + vcol);
            }
            __syncthreads();

#pragma unroll
            for (int cc = 0; cc < 16; ++cc) {
                float p8[8], v8[8];
                *(float4*)(p8)     = *(const float4*)&St[(c0 + cc) * 132 + prb];
                *(float4*)(p8 + 4) = *(const float4*)&St[(c0 + cc) * 132 + prb + 4];
                *(float4*)(v8)     = *(const float4*)&Vs[cc * 132 + pdb];
                *(float4*)(v8 + 4) = *(const float4*)&Vs[cc * 132 + pdb + 4];
#pragma unroll
                for (int i = 0; i < 8; ++i)
#pragma unroll
                    for (int j = 0; j < 8; ++j) acc_o[i][j] += p8[i] * v8[j];
            }
        }
        __syncthreads();   // protect St before next tile overwrites it
    }

    // epilogue: divide by l, write O[b, q0+r, h, d]
#pragma unroll
    for (int i = 0; i < 8; ++i) {
        const float inv = 1.0f / row_l[prb + i];
        float* op = O + ((size_t)(b * L_ + q0 + prb + i) * NH_ + h) * HD_ + pdb;
        *(float4*)(op)     = make_float4(acc_o[i][0] * inv, acc_o[i][1] * inv,
                                         acc_o[i][2] * inv, acc_o[i][3] * inv);
        *(float4*)(op + 4) = make_float4(acc_o[i][4] * inv, acc_o[i][5] * inv,
                                         acc_o[i][6] * inv, acc_o[i][7] * inv);
    }
}

// ---------------------------------------------------------------------------
extern "C" void kernel_launch(void* const* d_in, const int* in_sizes, int n_in,
                              void* d_out, int out_size) {
    const float* x  = (const float*)d_in[0];
    const float* Wq = (const float*)d_in[1];
    const float* Wk = (const float*)d_in[2];
    const float* Wv = (const float*)d_in[3];
    const float* Wo = (const float*)d_in[4];
    float* out = (float*)d_out;

    float *q, *k, *v, *o;
    cudaGetSymbolAddress((void**)&q, g_q);
    cudaGetSymbolAddress((void**)&k, g_k);
    cudaGetSymbolAddress((void**)&v, g_v);
    cudaGetSymbolAddress((void**)&o, g_o);

    const int M = B_ * L_;  // 4096

    rope_table_kernel<<<(L_ * 64 + 255) / 256, 256>>>();

    sgemm_nt<<<dim3(D_ / 128, M / 128), 256>>>(x, Wq, q, M, D_, D_);
    sgemm_nt<<<dim3((NKV_ * HD_) / 128, M / 128), 256>>>(x, Wk, k, M, NKV_ * HD_, D_);
    sgemm_nt<<<dim3((NKV_ * HD_) / 128, M / 128), 256>>>(x, Wv, v, M, NKV_ * HD_, D_);

    {
        const long long total = (long long)B_ * L_ * (NH_ + NKV_) * 64;
        const int blocks = (int)((total + 255) / 256);
        rope_apply_kernel<<<blocks, 256>>>(q, k);
    }

    cudaFuncSetAttribute(flash_attn3, cudaFuncAttributeMaxDynamicSharedMemorySize,
                         F3_SMEM);
    flash_attn3<<<dim3(L_ / 128, NH_, B_), 256, F3_SMEM>>>(q, k, v, o);

    sgemm_nt<<<dim3(D_ / 128, M / 128), 256>>>(o, Wo, out, M, D_, D_);
}

// round 6
// speedup vs baseline: 1.4532x; 1.4532x over previous
#include <cuda_runtime.h>
#include <cuda_bf16.h>
#include <math.h>
#include <stdint.h>

#define B_  2
#define L_  2048
#define D_  2048
#define NH_ 16
#define NKV_ 8
#define HD_ 128
#define GQ_ 2
#define SCALE_ 0.08838834764831845f  // 128^-0.5

// ---------------- scratch (static device globals) ----------------
__device__ float g_q[(size_t)B_ * L_ * NH_ * HD_];
__device__ float g_k[(size_t)B_ * L_ * NKV_ * HD_];
__device__ float g_v[(size_t)B_ * L_ * NKV_ * HD_];
__device__ float g_o[(size_t)B_ * L_ * NH_ * HD_];
__device__ float g_cos[(size_t)L_ * 64];
__device__ float g_sin[(size_t)L_ * 64];

__device__ __nv_bfloat16 g_xh[(size_t)B_ * L_ * D_];
__device__ __nv_bfloat16 g_xl[(size_t)B_ * L_ * D_];
__device__ __nv_bfloat16 g_wqh[(size_t)D_ * D_];
__device__ __nv_bfloat16 g_wql[(size_t)D_ * D_];
__device__ __nv_bfloat16 g_wkh[(size_t)NKV_ * HD_ * D_];
__device__ __nv_bfloat16 g_wkl[(size_t)NKV_ * HD_ * D_];
__device__ __nv_bfloat16 g_wvh[(size_t)NKV_ * HD_ * D_];
__device__ __nv_bfloat16 g_wvl[(size_t)NKV_ * HD_ * D_];
__device__ __nv_bfloat16 g_woh[(size_t)D_ * D_];
__device__ __nv_bfloat16 g_wol[(size_t)D_ * D_];
__device__ __nv_bfloat16 g_oh[(size_t)B_ * L_ * D_];
__device__ __nv_bfloat16 g_ol[(size_t)B_ * L_ * D_];

// ---------------- warp-mma helpers (base PTX, sm_80+) ----------------
__device__ __forceinline__ uint32_t smem_u32(const void* p) {
    uint32_t a;
    asm("{ .reg .u64 t; cvta.to.shared.u64 t, %1; cvt.u32.u64 %0, t; }"
        : "=r"(a) : "l"(p));
    return a;
}
#define LDSM4(r, a) \
    asm volatile("ldmatrix.sync.aligned.m8n8.x4.shared.b16 {%0,%1,%2,%3}, [%4];" \
                 : "=r"((r)[0]), "=r"((r)[1]), "=r"((r)[2]), "=r"((r)[3]) : "r"(a))
#define LDSM2(r, a) \
    asm volatile("ldmatrix.sync.aligned.m8n8.x2.shared.b16 {%0,%1}, [%2];" \
                 : "=r"((r)[0]), "=r"((r)[1]) : "r"(a))
#define MMA16816(d, a, b) \
    asm volatile("mma.sync.aligned.m16n8k16.row.col.f32.bf16.bf16.f32 " \
                 "{%0,%1,%2,%3}, {%4,%5,%6,%7}, {%8,%9}, {%0,%1,%2,%3};" \
                 : "+f"((d)[0]), "+f"((d)[1]), "+f"((d)[2]), "+f"((d)[3]) \
                 : "r"((a)[0]), "r"((a)[1]), "r"((a)[2]), "r"((a)[3]), \
                   "r"((b)[0]), "r"((b)[1]))

// ---------------------------------------------------------------------------
// split: fp32 -> bf16 hi + bf16 lo
// ---------------------------------------------------------------------------
__global__ void split_bf16(const float* __restrict__ s,
                           __nv_bfloat16* __restrict__ h,
                           __nv_bfloat16* __restrict__ l, int n4) {
    const int i = blockIdx.x * blockDim.x + threadIdx.x;
    if (i >= n4) return;
    const float4 v = ((const float4*)s)[i];
    __nv_bfloat16 h0 = __float2bfloat16_rn(v.x);
    __nv_bfloat16 h1 = __float2bfloat16_rn(v.y);
    __nv_bfloat16 h2 = __float2bfloat16_rn(v.z);
    __nv_bfloat16 h3 = __float2bfloat16_rn(v.w);
    h[i * 4 + 0] = h0; h[i * 4 + 1] = h1; h[i * 4 + 2] = h2; h[i * 4 + 3] = h3;
    l[i * 4 + 0] = __float2bfloat16_rn(v.x - __bfloat162float(h0));
    l[i * 4 + 1] = __float2bfloat16_rn(v.y - __bfloat162float(h1));
    l[i * 4 + 2] = __float2bfloat16_rn(v.z - __bfloat162float(h2));
    l[i * 4 + 3] = __float2bfloat16_rn(v.w - __bfloat162float(h3));
}

// ---------------------------------------------------------------------------
// mma.sync bf16x3 GEMM: C[M,N] = A[M,K] @ B[N,K]^T, fp32 out.
// 128x128 tile, K-chunk 64, 8 warps (2x4), each warp 64x32.
// ---------------------------------------------------------------------------
#define GP 72                     // smem pitch in bf16 (64 + 8 pad)
#define GT_TILE (128 * GP)        // bf16 elems per tile buffer
#define GT_SMEM (4 * GT_TILE * 2) // bytes

__global__ void __launch_bounds__(256) gemm_mma(const __nv_bfloat16* __restrict__ Ah,
                                                const __nv_bfloat16* __restrict__ Al,
                                                const __nv_bfloat16* __restrict__ Bh,
                                                const __nv_bfloat16* __restrict__ Bl,
                                                float* __restrict__ C,
                                                int N, int K) {
    extern __shared__ __nv_bfloat16 sb[];
    __nv_bfloat16* Ash = sb;
    __nv_bfloat16* Asl = sb + GT_TILE;
    __nv_bfloat16* Bsh = sb + 2 * GT_TILE;
    __nv_bfloat16* Bsl = sb + 3 * GT_TILE;

    const int tid = threadIdx.x;
    const int lane = tid & 31;
    const int wid = tid >> 5;
    const int wm = (wid >> 2) * 64;   // 0 or 64
    const int wn = (wid & 3) * 32;    // 0,32,64,96
    const int m0 = blockIdx.y * 128;
    const int n0 = blockIdx.x * 128;

    // staging: thread -> row tid/2, 4 consecutive 16B units at (tid&1)*4
    const int srow = tid >> 1;
    const int sub  = (tid & 1) * 4;   // unit index base (unit = 8 bf16)

    float acc[4][4][4];
#pragma unroll
    for (int i = 0; i < 4; ++i)
#pragma unroll
        for (int j = 0; j < 4; ++j)
#pragma unroll
            for (int q = 0; q < 4; ++q) acc[i][j][q] = 0.f;

    // fragment smem addresses (constant across chunks)
    const int arow = lane & 15, acol = (lane >> 4) << 3;
    const int brow = lane & 7,  bcol = ((lane >> 3) & 1) << 3;
    const uint32_t a_h0 = smem_u32(Ash + (wm + arow) * GP + acol);
    const uint32_t a_l0 = smem_u32(Asl + (wm + arow) * GP + acol);
    const uint32_t b_h0 = smem_u32(Bsh + (wn + brow) * GP + bcol);
    const uint32_t b_l0 = smem_u32(Bsl + (wn + brow) * GP + bcol);

    for (int kc = 0; kc < K; kc += 64) {
        // ---- stage 4 tiles (128 rows x 64 bf16) ----
        {
            const char* gA = (const char*)(Ah + (size_t)(m0 + srow) * K + kc);
            const char* gAl = (const char*)(Al + (size_t)(m0 + srow) * K + kc);
            const char* gB = (const char*)(Bh + (size_t)(n0 + srow) * K + kc);
            const char* gBl = (const char*)(Bl + (size_t)(n0 + srow) * K + kc);
            char* dA  = (char*)(Ash + srow * GP);
            char* dAl = (char*)(Asl + srow * GP);
            char* dB  = (char*)(Bsh + srow * GP);
            char* dBl = (char*)(Bsl + srow * GP);
#pragma unroll
            for (int u = 0; u < 4; ++u) {
                const int off = (sub + u) * 16;
                *(float4*)(dA + off)  = *(const float4*)(gA + off);
                *(float4*)(dAl + off) = *(const float4*)(gAl + off);
                *(float4*)(dB + off)  = *(const float4*)(gB + off);
                *(float4*)(dBl + off) = *(const float4*)(gBl + off);
            }
        }
        __syncthreads();

#pragma unroll
        for (int ks = 0; ks < 4; ++ks) {
            const uint32_t koff = ks * 16 * 2;  // bytes along k
            uint32_t ah[4][4], al[4][4], bh[4][2], bl[4][2];
#pragma unroll
            for (int mi = 0; mi < 4; ++mi) {
                LDSM4(ah[mi], a_h0 + mi * 16 * GP * 2 + koff);
                LDSM4(al[mi], a_l0 + mi * 16 * GP * 2 + koff);
            }
#pragma unroll
            for (int ni = 0; ni < 4; ++ni) {
                LDSM2(bh[ni], b_h0 + ni * 8 * GP * 2 + koff);
                LDSM2(bl[ni], b_l0 + ni * 8 * GP * 2 + koff);
            }
#pragma unroll
            for (int mi = 0; mi < 4; ++mi)
#pragma unroll
                for (int ni = 0; ni < 4; ++ni) {
                    MMA16816(acc[mi][ni], ah[mi], bh[ni]);
                    MMA16816(acc[mi][ni], ah[mi], bl[ni]);
                    MMA16816(acc[mi][ni], al[mi], bh[ni]);
                }
        }
        __syncthreads();
    }

    // epilogue: c0,c1 -> row m + lane/4, cols 2*(lane%4); c2,c3 -> row +8
    const int erow = lane >> 2;
    const int ecol = (lane & 3) * 2;
#pragma unroll
    for (int mi = 0; mi < 4; ++mi)
#pragma unroll
        for (int ni = 0; ni < 4; ++ni) {
            float* cp = C + (size_t)(m0 + wm + mi * 16 + erow) * N + n0 + wn + ni * 8 + ecol;
            *(float2*)cp = make_float2(acc[mi][ni][0], acc[mi][ni][1]);
            *(float2*)(cp + 8 * (size_t)N) = make_float2(acc[mi][ni][2], acc[mi][ni][3]);
        }
}

// ---------------------------------------------------------------------------
// RoPE table + apply
// ---------------------------------------------------------------------------
__global__ void rope_table_kernel() {
    const int idx = blockIdx.x * blockDim.x + threadIdx.x;
    if (idx >= L_ * 64) return;
    const int i = idx & 63;
    const int pos = idx >> 6;
    const double inv = exp(-(double)i / 64.0 * log(10000.0));
    double sd, cd;
    sincos((double)pos * inv, &sd, &cd);
    g_cos[idx] = (float)cd;
    g_sin[idx] = (float)sd;
}

__global__ void rope_apply_kernel(float* __restrict__ q, float* __restrict__ k) {
    const long long idx = (long long)blockIdx.x * blockDim.x + threadIdx.x;
    const long long total = (long long)B_ * L_ * (NH_ + NKV_) * 64;
    if (idx >= total) return;

    const int i  = (int)(idx & 63);
    long long r  = idx >> 6;
    const int hh = (int)(r % (NH_ + NKV_));
    r /= (NH_ + NKV_);
    const int bl  = (int)r;
    const int pos = bl & (L_ - 1);

    float* ptr;
    if (hh < NH_) ptr = q + ((size_t)bl * NH_ + hh) * HD_;
    else          ptr = k + ((size_t)bl * NKV_ + (hh - NH_)) * HD_;

    const float c = g_cos[pos * 64 + i];
    const float s = g_sin[pos * 64 + i];
    const float a = ptr[i];
    const float b = ptr[i + 64];
    ptr[i]      = a * c - b * s;
    ptr[i + 64] = b * c + a * s;
}

// ---------------------------------------------------------------------------
// Flash attention v2 (best SIMT version, round 2)
// ---------------------------------------------------------------------------
__global__ void __launch_bounds__(256) flash_attn2(const float* __restrict__ Q,
                                                   const float* __restrict__ K,
                                                   const float* __restrict__ V,
                                                   float* __restrict__ O) {
    __shared__ float St[64 * 132];
    __shared__ float QVs[16 * 132];
    __shared__ float Ks[16 * 68];
    __shared__ float row_m[128], row_l[128], row_a[128];

    const int tid = threadIdx.x;
    const int b = blockIdx.z, h = blockIdx.y;
    const int kvh = h >> 1;
    const int qt = (gridDim.x - 1) - blockIdx.x;
    const int q0 = qt * 128;

    const int lr = tid >> 2;
    const int lc = (tid & 3) << 2;
    const int vrow = tid >> 5;
    const int vcol = (tid & 31) << 2;

    const int cb = (tid >> 4) << 2;
    const int rb = (tid & 15) << 3;
    const int prb = (tid >> 4) << 3;
    const int pdb = (tid & 15) << 3;

    const float* Qg = Q + ((size_t)(b * L_ + q0) * NH_ + h) * HD_;
    const float* Kg = K + ((size_t)(b * L_) * NKV_ + kvh) * HD_;
    const float* Vg = V + ((size_t)(b * L_) * NKV_ + kvh) * HD_;

    if (tid < 128) { row_m[tid] = -1e30f; row_l[tid] = 0.f; }

    float acc_o[8][8];
#pragma unroll
    for (int i = 0; i < 8; ++i)
#pragma unroll
        for (int j = 0; j < 8; ++j) acc_o[i][j] = 0.f;

    const int tmax = 2 * qt + 2;
    for (int t = 0; t < tmax; ++t) {
        const int k0 = t * 64;

        float acc_s[4][8];
#pragma unroll
        for (int j = 0; j < 4; ++j)
#pragma unroll
            for (int i = 0; i < 8; ++i) acc_s[j][i] = 0.f;

        float4 kp  = *(const float4*)(Kg + (size_t)(k0 + lr) * (NKV_ * HD_) + lc);
        float4 qp0 = *(const float4*)(Qg + (size_t)lr        * (NH_ * HD_) + lc);
        float4 qp1 = *(const float4*)(Qg + (size_t)(lr + 64) * (NH_ * HD_) + lc);

        for (int d0 = 0; d0 < HD_; d0 += 16) {
            __syncthreads();
            Ks[(lc + 0) * 68 + lr] = kp.x;  Ks[(lc + 1) * 68 + lr] = kp.y;
            Ks[(lc + 2) * 68 + lr] = kp.z;  Ks[(lc + 3) * 68 + lr] = kp.w;
            QVs[(lc + 0) * 132 + lr] = qp0.x;  QVs[(lc + 1) * 132 + lr] = qp0.y;
            QVs[(lc + 2) * 132 + lr] = qp0.z;  QVs[(lc + 3) * 132 + lr] = qp0.w;
            QVs[(lc + 0) * 132 + lr + 64] = qp1.x;  QVs[(lc + 1) * 132 + lr + 64] = qp1.y;
            QVs[(lc + 2) * 132 + lr + 64] = qp1.z;  QVs[(lc + 3) * 132 + lr + 64] = qp1.w;
            __syncthreads();

            if (d0 + 16 < HD_) {
                kp  = *(const float4*)(Kg + (size_t)(k0 + lr) * (NKV_ * HD_) + d0 + 16 + lc);
                qp0 = *(const float4*)(Qg + (size_t)lr        * (NH_ * HD_) + d0 + 16 + lc);
                qp1 = *(const float4*)(Qg + (size_t)(lr + 64) * (NH_ * HD_) + d0 + 16 + lc);
            }

#pragma unroll
            for (int kk = 0; kk < 16; ++kk) {
                float kr[4], qr[8];
                *(float4*)(kr)     = *(const float4*)&Ks[kk * 68 + cb];
                *(float4*)(qr)     = *(const float4*)&QVs[kk * 132 + rb];
                *(float4*)(qr + 4) = *(const float4*)&QVs[kk * 132 + rb + 4];
#pragma unroll
                for (int j = 0; j < 4; ++j)
#pragma unroll
                    for (int i = 0; i < 8; ++i) acc_s[j][i] += kr[j] * qr[i];
            }
        }

        __syncthreads();
#pragma unroll
        for (int j = 0; j < 4; ++j) {
            const int thr = (k0 + cb + j) - (q0 + rb);
#pragma unroll
            for (int ih = 0; ih < 2; ++ih) {
                float4 o;
                o.x = (ih * 4 + 0 >= thr) ? acc_s[j][ih * 4 + 0] * SCALE_ : -1e30f;
                o.y = (ih * 4 + 1 >= thr) ? acc_s[j][ih * 4 + 1] * SCALE_ : -1e30f;
                o.z = (ih * 4 + 2 >= thr) ? acc_s[j][ih * 4 + 2] * SCALE_ : -1e30f;
                o.w = (ih * 4 + 3 >= thr) ? acc_s[j][ih * 4 + 3] * SCALE_ : -1e30f;
                *(float4*)&St[(cb + j) * 132 + rb + ih * 4] = o;
            }
        }
        __syncthreads();

        {
            const int r = tid >> 1, sub = tid & 1;
            float* colp = St + r + (sub << 5) * 132;
            float mx = -1e30f;
#pragma unroll 8
            for (int c = 0; c < 32; ++c) mx = fmaxf(mx, colp[c * 132]);
            mx = fmaxf(mx, __shfl_xor_sync(0xffffffffu, mx, 1));
            const float oldm = row_m[r];
            const float nm = fmaxf(mx, oldm);
            float sum = 0.f;
#pragma unroll 8
            for (int c = 0; c < 32; ++c) {
                const float p = __expf(colp[c * 132] - nm);
                colp[c * 132] = p;
                sum += p;
            }
            sum += __shfl_xor_sync(0xffffffffu, sum, 1);
            if (sub == 0) {
                const float al = __expf(oldm - nm);
                row_a[r] = al;
                row_l[r] = row_l[r] * al + sum;
                row_m[r] = nm;
            }
        }
        __syncthreads();

#pragma unroll
        for (int i = 0; i < 8; ++i) {
            const float al = row_a[prb + i];
#pragma unroll
            for (int j = 0; j < 8; ++j) acc_o[i][j] *= al;
        }

        float4 vp0 = *(const float4*)(Vg + (size_t)(k0 + vrow)     * (NKV_ * HD_) + vcol);
        float4 vp1 = *(const float4*)(Vg + (size_t)(k0 + vrow + 8) * (NKV_ * HD_) + vcol);

        for (int c0 = 0; c0 < 64; c0 += 16) {
            __syncthreads();
            *(float4*)&QVs[vrow * 132 + vcol]       = vp0;
            *(float4*)&QVs[(vrow + 8) * 132 + vcol] = vp1;
            __syncthreads();

            if (c0 + 16 < 64) {
                vp0 = *(const float4*)(Vg + (size_t)(k0 + c0 + 16 + vrow)     * (NKV_ * HD_) + vcol);
                vp1 = *(const float4*)(Vg + (size_t)(k0 + c0 + 16 + vrow + 8) * (NKV_ * HD_) + vcol);
            }

#pragma unroll
            for (int cc = 0; cc < 16; ++cc) {
                float p8[8], v8[8];
                *(float4*)(p8)     = *(const float4*)&St[(c0 + cc) * 132 + prb];
                *(float4*)(p8 + 4) = *(const float4*)&St[(c0 + cc) * 132 + prb + 4];
                *(float4*)(v8)     = *(const float4*)&QVs[cc * 132 + pdb];
                *(float4*)(v8 + 4) = *(const float4*)&QVs[cc * 132 + pdb + 4];
#pragma unroll
                for (int i = 0; i < 8; ++i)
#pragma unroll
                    for (int j = 0; j < 8; ++j) acc_o[i][j] += p8[i] * v8[j];
            }
        }
    }

#pragma unroll
    for (int i = 0; i < 8; ++i) {
        const float inv = 1.0f / row_l[prb + i];
        float* op = O + ((size_t)(b * L_ + q0 + prb + i) * NH_ + h) * HD_ + pdb;
        *(float4*)(op)     = make_float4(acc_o[i][0] * inv, acc_o[i][1] * inv,
                                         acc_o[i][2] * inv, acc_o[i][3] * inv);
        *(float4*)(op + 4) = make_float4(acc_o[i][4] * inv, acc_o[i][5] * inv,
                                         acc_o[i][6] * inv, acc_o[i][7] * inv);
    }
}

// ---------------------------------------------------------------------------
extern "C" void kernel_launch(void* const* d_in, const int* in_sizes, int n_in,
                              void* d_out, int out_size) {
    const float* x  = (const float*)d_in[0];
    const float* Wq = (const float*)d_in[1];
    const float* Wk = (const float*)d_in[2];
    const float* Wv = (const float*)d_in[3];
    const float* Wo = (const float*)d_in[4];
    float* out = (float*)d_out;

    float *q, *k, *v, *o;
    cudaGetSymbolAddress((void**)&q, g_q);
    cudaGetSymbolAddress((void**)&k, g_k);
    cudaGetSymbolAddress((void**)&v, g_v);
    cudaGetSymbolAddress((void**)&o, g_o);
    __nv_bfloat16 *xh, *xl, *wqh, *wql, *wkh, *wkl, *wvh, *wvl, *woh, *wol, *oh, *ol;
    cudaGetSymbolAddress((void**)&xh, g_xh);   cudaGetSymbolAddress((void**)&xl, g_xl);
    cudaGetSymbolAddress((void**)&wqh, g_wqh); cudaGetSymbolAddress((void**)&wql, g_wql);
    cudaGetSymbolAddress((void**)&wkh, g_wkh); cudaGetSymbolAddress((void**)&wkl, g_wkl);
    cudaGetSymbolAddress((void**)&wvh, g_wvh); cudaGetSymbolAddress((void**)&wvl, g_wvl);
    cudaGetSymbolAddress((void**)&woh, g_woh); cudaGetSymbolAddress((void**)&wol, g_wol);
    cudaGetSymbolAddress((void**)&oh, g_oh);   cudaGetSymbolAddress((void**)&ol, g_ol);

    const int M = B_ * L_;       // 4096
    const int NKVD = NKV_ * HD_; // 1024

    cudaFuncSetAttribute(gemm_mma, cudaFuncAttributeMaxDynamicSharedMemorySize, GT_SMEM);

    rope_table_kernel<<<(L_ * 64 + 255) / 256, 256>>>();

    // split inputs/weights into bf16 hi/lo
    split_bf16<<<(M * D_ / 4 + 255) / 256, 256>>>(x, xh, xl, M * D_ / 4);
    split_bf16<<<(D_ * D_ / 4 + 255) / 256, 256>>>(Wq, wqh, wql, D_ * D_ / 4);
    split_bf16<<<(NKVD * D_ / 4 + 255) / 256, 256>>>(Wk, wkh, wkl, NKVD * D_ / 4);
    split_bf16<<<(NKVD * D_ / 4 + 255) / 256, 256>>>(Wv, wvh, wvl, NKVD * D_ / 4);
    split_bf16<<<(D_ * D_ / 4 + 255) / 256, 256>>>(Wo, woh, wol, D_ * D_ / 4);

    // projections (tensor cores via mma.sync)
    gemm_mma<<<dim3(D_ / 128, M / 128), 256, GT_SMEM>>>(xh, xl, wqh, wql, q, D_, D_);
    gemm_mma<<<dim3(NKVD / 128, M / 128), 256, GT_SMEM>>>(xh, xl, wkh, wkl, k, NKVD, D_);
    gemm_mma<<<dim3(NKVD / 128, M / 128), 256, GT_SMEM>>>(xh, xl, wvh, wvl, v, NKVD, D_);

    {
        const long long total = (long long)B_ * L_ * (NH_ + NKV_) * 64;
        const int blocks = (int)((total + 255) / 256);
        rope_apply_kernel<<<blocks, 256>>>(q, k);
    }

    flash_attn2<<<dim3(L_ / 128, NH_, B_), 256>>>(q, k, v, o);

    // output projection
    split_bf16<<<(M * D_ / 4 + 255) / 256, 256>>>(o, oh, ol, M * D_ / 4);
    gemm_mma<<<dim3(D_ / 128, M / 128), 256, GT_SMEM>>>(oh, ol, woh, wol, out, D_, D_);
}

// round 7
// speedup vs baseline: 1.8679x; 1.2854x over previous
#include <cuda_runtime.h>
#include <cuda_bf16.h>
#include <math.h>
#include <stdint.h>

#define B_  2
#define L_  2048
#define D_  2048
#define NH_ 16
#define NKV_ 8
#define HD_ 128
#define GQ_ 2
#define SCALE_ 0.08838834764831845f  // 128^-0.5

// ---------------- scratch (static device globals) ----------------
__device__ float g_q[(size_t)B_ * L_ * NH_ * HD_];
__device__ float g_k[(size_t)B_ * L_ * NKV_ * HD_];
__device__ float g_v[(size_t)B_ * L_ * NKV_ * HD_];
__device__ float g_o[(size_t)B_ * L_ * NH_ * HD_];
__device__ float g_cos[(size_t)L_ * 64];
__device__ float g_sin[(size_t)L_ * 64];

__device__ __nv_bfloat16 g_xh[(size_t)B_ * L_ * D_];
__device__ __nv_bfloat16 g_xl[(size_t)B_ * L_ * D_];
__device__ __nv_bfloat16 g_wqh[(size_t)D_ * D_];
__device__ __nv_bfloat16 g_wql[(size_t)D_ * D_];
__device__ __nv_bfloat16 g_wkh[(size_t)NKV_ * HD_ * D_];
__device__ __nv_bfloat16 g_wkl[(size_t)NKV_ * HD_ * D_];
__device__ __nv_bfloat16 g_wvh[(size_t)NKV_ * HD_ * D_];
__device__ __nv_bfloat16 g_wvl[(size_t)NKV_ * HD_ * D_];
__device__ __nv_bfloat16 g_woh[(size_t)D_ * D_];
__device__ __nv_bfloat16 g_wol[(size_t)D_ * D_];
__device__ __nv_bfloat16 g_oh[(size_t)B_ * L_ * D_];
__device__ __nv_bfloat16 g_ol[(size_t)B_ * L_ * D_];

// ---------------- warp-mma helpers ----------------
__device__ __forceinline__ uint32_t smem_u32(const void* p) {
    uint32_t a;
    asm("{ .reg .u64 t; cvta.to.shared.u64 t, %1; cvt.u32.u64 %0, t; }"
        : "=r"(a) : "l"(p));
    return a;
}
#define LDSM4(r, a) \
    asm volatile("ldmatrix.sync.aligned.m8n8.x4.shared.b16 {%0,%1,%2,%3}, [%4];" \
                 : "=r"((r)[0]), "=r"((r)[1]), "=r"((r)[2]), "=r"((r)[3]) : "r"(a))
#define LDSM2(r, a) \
    asm volatile("ldmatrix.sync.aligned.m8n8.x2.shared.b16 {%0,%1}, [%2];" \
                 : "=r"((r)[0]), "=r"((r)[1]) : "r"(a))
#define MMA16816(d, a, b) \
    asm volatile("mma.sync.aligned.m16n8k16.row.col.f32.bf16.bf16.f32 " \
                 "{%0,%1,%2,%3}, {%4,%5,%6,%7}, {%8,%9}, {%0,%1,%2,%3};" \
                 : "+f"((d)[0]), "+f"((d)[1]), "+f"((d)[2]), "+f"((d)[3]) \
                 : "r"((a)[0]), "r"((a)[1]), "r"((a)[2]), "r"((a)[3]), \
                   "r"((b)[0]), "r"((b)[1]))

__device__ __forceinline__ uint32_t packbf2(__nv_bfloat16 lo, __nv_bfloat16 hi) {
    __nv_bfloat162 t = __halves2bfloat162(lo, hi);  // x=lo, y=hi
    return *(uint32_t*)&t;
}

// ---------------------------------------------------------------------------
// split: fp32 -> bf16 hi + bf16 lo
// ---------------------------------------------------------------------------
__global__ void split_bf16(const float* __restrict__ s,
                           __nv_bfloat16* __restrict__ h,
                           __nv_bfloat16* __restrict__ l, int n4) {
    const int i = blockIdx.x * blockDim.x + threadIdx.x;
    if (i >= n4) return;
    const float4 v = ((const float4*)s)[i];
    __nv_bfloat16 h0 = __float2bfloat16_rn(v.x);
    __nv_bfloat16 h1 = __float2bfloat16_rn(v.y);
    __nv_bfloat16 h2 = __float2bfloat16_rn(v.z);
    __nv_bfloat16 h3 = __float2bfloat16_rn(v.w);
    h[i * 4 + 0] = h0; h[i * 4 + 1] = h1; h[i * 4 + 2] = h2; h[i * 4 + 3] = h3;
    l[i * 4 + 0] = __float2bfloat16_rn(v.x - __bfloat162float(h0));
    l[i * 4 + 1] = __float2bfloat16_rn(v.y - __bfloat162float(h1));
    l[i * 4 + 2] = __float2bfloat16_rn(v.z - __bfloat162float(h2));
    l[i * 4 + 3] = __float2bfloat16_rn(v.w - __bfloat162float(h3));
}

// ---------------------------------------------------------------------------
// mma.sync bf16x3 GEMM (validated in round 5)
// ---------------------------------------------------------------------------
#define GP 72
#define GT_TILE (128 * GP)
#define GT_SMEM (4 * GT_TILE * 2)

__global__ void __launch_bounds__(256) gemm_mma(const __nv_bfloat16* __restrict__ Ah,
                                                const __nv_bfloat16* __restrict__ Al,
                                                const __nv_bfloat16* __restrict__ Bh,
                                                const __nv_bfloat16* __restrict__ Bl,
                                                float* __restrict__ C,
                                                int N, int K) {
    extern __shared__ __nv_bfloat16 sb[];
    __nv_bfloat16* Ash = sb;
    __nv_bfloat16* Asl = sb + GT_TILE;
    __nv_bfloat16* Bsh = sb + 2 * GT_TILE;
    __nv_bfloat16* Bsl = sb + 3 * GT_TILE;

    const int tid = threadIdx.x;
    const int lane = tid & 31;
    const int wid = tid >> 5;
    const int wm = (wid >> 2) * 64;
    const int wn = (wid & 3) * 32;
    const int m0 = blockIdx.y * 128;
    const int n0 = blockIdx.x * 128;

    const int srow = tid >> 1;
    const int sub  = (tid & 1) * 4;

    float acc[4][4][4];
#pragma unroll
    for (int i = 0; i < 4; ++i)
#pragma unroll
        for (int j = 0; j < 4; ++j)
#pragma unroll
            for (int q = 0; q < 4; ++q) acc[i][j][q] = 0.f;

    const int arow = lane & 15, acol = (lane >> 4) << 3;
    const int brow = lane & 7,  bcol = ((lane >> 3) & 1) << 3;
    const uint32_t a_h0 = smem_u32(Ash + (wm + arow) * GP + acol);
    const uint32_t a_l0 = smem_u32(Asl + (wm + arow) * GP + acol);
    const uint32_t b_h0 = smem_u32(Bsh + (wn + brow) * GP + bcol);
    const uint32_t b_l0 = smem_u32(Bsl + (wn + brow) * GP + bcol);

    for (int kc = 0; kc < K; kc += 64) {
        {
            const char* gA = (const char*)(Ah + (size_t)(m0 + srow) * K + kc);
            const char* gAl = (const char*)(Al + (size_t)(m0 + srow) * K + kc);
            const char* gB = (const char*)(Bh + (size_t)(n0 + srow) * K + kc);
            const char* gBl = (const char*)(Bl + (size_t)(n0 + srow) * K + kc);
            char* dA  = (char*)(Ash + srow * GP);
            char* dAl = (char*)(Asl + srow * GP);
            char* dB  = (char*)(Bsh + srow * GP);
            char* dBl = (char*)(Bsl + srow * GP);
#pragma unroll
            for (int u = 0; u < 4; ++u) {
                const int off = (sub + u) * 16;
                *(float4*)(dA + off)  = *(const float4*)(gA + off);
                *(float4*)(dAl + off) = *(const float4*)(gAl + off);
                *(float4*)(dB + off)  = *(const float4*)(gB + off);
                *(float4*)(dBl + off) = *(const float4*)(gBl + off);
            }
        }
        __syncthreads();

#pragma unroll
        for (int ks = 0; ks < 4; ++ks) {
            const uint32_t koff = ks * 16 * 2;
            uint32_t ah[4][4], al[4][4], bh[4][2], bl[4][2];
#pragma unroll
            for (int mi = 0; mi < 4; ++mi) {
                LDSM4(ah[mi], a_h0 + mi * 16 * GP * 2 + koff);
                LDSM4(al[mi], a_l0 + mi * 16 * GP * 2 + koff);
            }
#pragma unroll
            for (int ni = 0; ni < 4; ++ni) {
                LDSM2(bh[ni], b_h0 + ni * 8 * GP * 2 + koff);
                LDSM2(bl[ni], b_l0 + ni * 8 * GP * 2 + koff);
            }
#pragma unroll
            for (int mi = 0; mi < 4; ++mi)
#pragma unroll
                for (int ni = 0; ni < 4; ++ni) {
                    MMA16816(acc[mi][ni], ah[mi], bh[ni]);
                    MMA16816(acc[mi][ni], ah[mi], bl[ni]);
                    MMA16816(acc[mi][ni], al[mi], bh[ni]);
                }
        }
        __syncthreads();
    }

    const int erow = lane >> 2;
    const int ecol = (lane & 3) * 2;
#pragma unroll
    for (int mi = 0; mi < 4; ++mi)
#pragma unroll
        for (int ni = 0; ni < 4; ++ni) {
            float* cp = C + (size_t)(m0 + wm + mi * 16 + erow) * N + n0 + wn + ni * 8 + ecol;
            *(float2*)cp = make_float2(acc[mi][ni][0], acc[mi][ni][1]);
            *(float2*)(cp + 8 * (size_t)N) = make_float2(acc[mi][ni][2], acc[mi][ni][3]);
        }
}

// ---------------------------------------------------------------------------
// RoPE table + apply
// ---------------------------------------------------------------------------
__global__ void rope_table_kernel() {
    const int idx = blockIdx.x * blockDim.x + threadIdx.x;
    if (idx >= L_ * 64) return;
    const int i = idx & 63;
    const int pos = idx >> 6;
    const double inv = exp(-(double)i / 64.0 * log(10000.0));
    double sd, cd;
    sincos((double)pos * inv, &sd, &cd);
    g_cos[idx] = (float)cd;
    g_sin[idx] = (float)sd;
}

__global__ void rope_apply_kernel(float* __restrict__ q, float* __restrict__ k) {
    const long long idx = (long long)blockIdx.x * blockDim.x + threadIdx.x;
    const long long total = (long long)B_ * L_ * (NH_ + NKV_) * 64;
    if (idx >= total) return;

    const int i  = (int)(idx & 63);
    long long r  = idx >> 6;
    const int hh = (int)(r % (NH_ + NKV_));
    r /= (NH_ + NKV_);
    const int bl  = (int)r;
    const int pos = bl & (L_ - 1);

    float* ptr;
    if (hh < NH_) ptr = q + ((size_t)bl * NH_ + hh) * HD_;
    else          ptr = k + ((size_t)bl * NKV_ + (hh - NH_)) * HD_;

    const float c = g_cos[pos * 64 + i];
    const float s = g_sin[pos * 64 + i];
    const float a = ptr[i];
    const float b = ptr[i + 64];
    ptr[i]      = a * c - b * s;
    ptr[i + 64] = b * c + a * s;
}

// ---------------------------------------------------------------------------
// Flash attention v4: mma.sync tensor-core flash, bf16x3 splits everywhere.
// CTA: 128 q-rows x one (b,h). 8 warps, each warp = 16 q-rows x 64 k-cols.
// smem: Qh/Ql [128][136], Kh/Kl [64][136], Vt_h/Vt_l [128 d][72 kpos] bf16.
// ---------------------------------------------------------------------------
#define FQP 136
#define FVP 72
#define FO_QH 0
#define FO_QL 34816
#define FO_KH 69632
#define FO_KL 87040
#define FO_VH 104448
#define FO_VL 122880
#define FM_SMEM 141312

__global__ void __launch_bounds__(256) flash_mma(const float* __restrict__ Q,
                                                 const float* __restrict__ K,
                                                 const float* __restrict__ V,
                                                 float* __restrict__ O) {
    extern __shared__ char smem[];
    __nv_bfloat16* Qh = (__nv_bfloat16*)(smem + FO_QH);
    __nv_bfloat16* Ql = (__nv_bfloat16*)(smem + FO_QL);
    __nv_bfloat16* Kh = (__nv_bfloat16*)(smem + FO_KH);
    __nv_bfloat16* Kl = (__nv_bfloat16*)(smem + FO_KL);
    __nv_bfloat16* Vh = (__nv_bfloat16*)(smem + FO_VH);
    __nv_bfloat16* Vl = (__nv_bfloat16*)(smem + FO_VL);

    const int tid = threadIdx.x;
    const int lane = tid & 31, wid = tid >> 5;
    const int b = blockIdx.z, h = blockIdx.y;
    const int kvh = h >> 1;
    const int qt = (gridDim.x - 1) - blockIdx.x;   // heavy tiles first
    const int q0 = qt * 128;
    const int wrow = wid * 16;

    const float* Qg = Q + ((size_t)(b * L_ + q0) * NH_ + h) * HD_;
    const float* Kg = K + ((size_t)(b * L_) * NKV_ + kvh) * HD_;
    const float* Vg = V + ((size_t)(b * L_) * NKV_ + kvh) * HD_;

    // ---- stage Q (once): [128 q][128 d] -> Qh/Ql [q][FQP] ----
    for (int i = tid; i < 128 * 32; i += 256) {
        const int row = i >> 5, c4 = (i & 31) << 2;
        const float4 v4 = *(const float4*)(Qg + (size_t)row * (NH_ * HD_) + c4);
        __nv_bfloat16 h0 = __float2bfloat16_rn(v4.x);
        __nv_bfloat16 h1 = __float2bfloat16_rn(v4.y);
        __nv_bfloat16 h2 = __float2bfloat16_rn(v4.z);
        __nv_bfloat16 h3 = __float2bfloat16_rn(v4.w);
        __nv_bfloat162* ph = (__nv_bfloat162*)(Qh + row * FQP + c4);
        ph[0] = __halves2bfloat162(h0, h1);
        ph[1] = __halves2bfloat162(h2, h3);
        __nv_bfloat162* pl = (__nv_bfloat162*)(Ql + row * FQP + c4);
        pl[0] = __halves2bfloat162(__float2bfloat16_rn(v4.x - __bfloat162float(h0)),
                                   __float2bfloat16_rn(v4.y - __bfloat162float(h1)));
        pl[1] = __halves2bfloat162(__float2bfloat16_rn(v4.z - __bfloat162float(h2)),
                                   __float2bfloat16_rn(v4.w - __bfloat162float(h3)));
    }

    // fragment smem base addresses
    const uint32_t aQh = smem_u32(Qh + (wrow + (lane & 15)) * FQP + ((lane >> 4) << 3));
    const uint32_t aQl = smem_u32(Ql + (wrow + (lane & 15)) * FQP + ((lane >> 4) << 3));
    const uint32_t bKh = smem_u32(Kh + (lane & 7) * FQP + (((lane >> 3) & 1) << 3));
    const uint32_t bKl = smem_u32(Kl + (lane & 7) * FQP + (((lane >> 3) & 1) << 3));
    const uint32_t bVh = smem_u32(Vh + (lane & 7) * FVP + (((lane >> 3) & 1) << 3));
    const uint32_t bVl = smem_u32(Vl + (lane & 7) * FVP + (((lane >> 3) & 1) << 3));

    float m0 = -1e30f, m1 = -1e30f, l0 = 0.f, l1 = 0.f;
    float ao[16][4];
#pragma unroll
    for (int i = 0; i < 16; ++i)
#pragma unroll
        for (int j = 0; j < 4; ++j) ao[i][j] = 0.f;

    const int tmax = 2 * qt + 2;
    for (int t = 0; t < tmax; ++t) {
        const int k0 = t * 64;

        __syncthreads();   // previous tile's smem reads complete
        // ---- stage K, V ----
        for (int i = tid; i < 64 * 32; i += 256) {
            const int row = i >> 5, c4 = (i & 31) << 2;
            const size_t g = (size_t)(k0 + row) * (NKV_ * HD_) + c4;
            const float4 kv = *(const float4*)(Kg + g);
            __nv_bfloat16 k0h = __float2bfloat16_rn(kv.x);
            __nv_bfloat16 k1h = __float2bfloat16_rn(kv.y);
            __nv_bfloat16 k2h = __float2bfloat16_rn(kv.z);
            __nv_bfloat16 k3h = __float2bfloat16_rn(kv.w);
            __nv_bfloat162* ph = (__nv_bfloat162*)(Kh + row * FQP + c4);
            ph[0] = __halves2bfloat162(k0h, k1h);
            ph[1] = __halves2bfloat162(k2h, k3h);
            __nv_bfloat162* pl = (__nv_bfloat162*)(Kl + row * FQP + c4);
            pl[0] = __halves2bfloat162(__float2bfloat16_rn(kv.x - __bfloat162float(k0h)),
                                       __float2bfloat16_rn(kv.y - __bfloat162float(k1h)));
            pl[1] = __halves2bfloat162(__float2bfloat16_rn(kv.z - __bfloat162float(k2h)),
                                       __float2bfloat16_rn(kv.w - __bfloat162float(k3h)));

            const float4 vv = *(const float4*)(Vg + g);
            const float vf[4] = {vv.x, vv.y, vv.z, vv.w};
#pragma unroll
            for (int j = 0; j < 4; ++j) {
                const __nv_bfloat16 vh = __float2bfloat16_rn(vf[j]);
                Vh[(c4 + j) * FVP + row] = vh;
                Vl[(c4 + j) * FVP + row] =
                    __float2bfloat16_rn(vf[j] - __bfloat162float(vh));
            }
        }
        __syncthreads();

        // ---- S = Q @ K^T (3-way split) ----
        float sc[8][4];
#pragma unroll
        for (int ni = 0; ni < 8; ++ni)
#pragma unroll
            for (int j = 0; j < 4; ++j) sc[ni][j] = 0.f;

#pragma unroll
        for (int ks = 0; ks < 8; ++ks) {
            const uint32_t koff = ks * 32;
            uint32_t ah[4], al[4];
            LDSM4(ah, aQh + koff);
            LDSM4(al, aQl + koff);
#pragma unroll
            for (int ni = 0; ni < 8; ++ni) {
                uint32_t bh[2], bl[2];
                LDSM2(bh, bKh + ni * (8 * FQP * 2) + koff);
                LDSM2(bl, bKl + ni * (8 * FQP * 2) + koff);
                MMA16816(sc[ni], ah, bh);
                MMA16816(sc[ni], ah, bl);
                MMA16816(sc[ni], al, bh);
            }
        }

        // scale + causal mask (diag tiles only)
#pragma unroll
        for (int ni = 0; ni < 8; ++ni)
#pragma unroll
            for (int j = 0; j < 4; ++j) sc[ni][j] *= SCALE_;

        if (t >= tmax - 2) {
            const int qr0 = q0 + wrow + (lane >> 2);
#pragma unroll
            for (int ni = 0; ni < 8; ++ni) {
                const int kc = k0 + ni * 8 + (lane & 3) * 2;
                if (kc > qr0)     sc[ni][0] = -1e30f;
                if (kc + 1 > qr0) sc[ni][1] = -1e30f;
                if (kc > qr0 + 8)     sc[ni][2] = -1e30f;
                if (kc + 1 > qr0 + 8) sc[ni][3] = -1e30f;
            }
        }

        // ---- online softmax (register-resident, 2 shuffles) ----
        float mx0 = -1e30f, mx1 = -1e30f;
#pragma unroll
        for (int ni = 0; ni < 8; ++ni) {
            mx0 = fmaxf(mx0, fmaxf(sc[ni][0], sc[ni][1]));
            mx1 = fmaxf(mx1, fmaxf(sc[ni][2], sc[ni][3]));
        }
        mx0 = fmaxf(mx0, __shfl_xor_sync(0xffffffffu, mx0, 1));
        mx0 = fmaxf(mx0, __shfl_xor_sync(0xffffffffu, mx0, 2));
        mx1 = fmaxf(mx1, __shfl_xor_sync(0xffffffffu, mx1, 1));
        mx1 = fmaxf(mx1, __shfl_xor_sync(0xffffffffu, mx1, 2));

        const float nm0 = fmaxf(m0, mx0), nm1 = fmaxf(m1, mx1);
        const float al0 = __expf(m0 - nm0), al1 = __expf(m1 - nm1);
        float s0 = 0.f, s1 = 0.f;
#pragma unroll
        for (int ni = 0; ni < 8; ++ni) {
            sc[ni][0] = __expf(sc[ni][0] - nm0); s0 += sc[ni][0];
            sc[ni][1] = __expf(sc[ni][1] - nm0); s0 += sc[ni][1];
            sc[ni][2] = __expf(sc[ni][2] - nm1); s1 += sc[ni][2];
            sc[ni][3] = __expf(sc[ni][3] - nm1); s1 += sc[ni][3];
        }
        s0 += __shfl_xor_sync(0xffffffffu, s0, 1);
        s0 += __shfl_xor_sync(0xffffffffu, s0, 2);
        s1 += __shfl_xor_sync(0xffffffffu, s1, 1);
        s1 += __shfl_xor_sync(0xffffffffu, s1, 2);
        l0 = l0 * al0 + s0; l1 = l1 * al1 + s1;
        m0 = nm0; m1 = nm1;

#pragma unroll
        for (int i = 0; i < 16; ++i) {
            ao[i][0] *= al0; ao[i][1] *= al0;
            ao[i][2] *= al1; ao[i][3] *= al1;
        }

        // ---- O += P @ V (P split in regs, V split in smem) ----
#pragma unroll
        for (int ks = 0; ks < 4; ++ks) {
            const float p0 = sc[2 * ks][0], p1 = sc[2 * ks][1];
            const float p2 = sc[2 * ks][2], p3 = sc[2 * ks][3];
            const float p4 = sc[2 * ks + 1][0], p5 = sc[2 * ks + 1][1];
            const float p6 = sc[2 * ks + 1][2], p7 = sc[2 * ks + 1][3];
            const __nv_bfloat16 q0b = __float2bfloat16_rn(p0), q1b = __float2bfloat16_rn(p1);
            const __nv_bfloat16 q2b = __float2bfloat16_rn(p2), q3b = __float2bfloat16_rn(p3);
            const __nv_bfloat16 q4b = __float2bfloat16_rn(p4), q5b = __float2bfloat16_rn(p5);
            const __nv_bfloat16 q6b = __float2bfloat16_rn(p6), q7b = __float2bfloat16_rn(p7);
            uint32_t pah[4], pal[4];
            pah[0] = packbf2(q0b, q1b);
            pah[1] = packbf2(q2b, q3b);
            pah[2] = packbf2(q4b, q5b);
            pah[3] = packbf2(q6b, q7b);
            pal[0] = packbf2(__float2bfloat16_rn(p0 - __bfloat162float(q0b)),
                             __float2bfloat16_rn(p1 - __bfloat162float(q1b)));
            pal[1] = packbf2(__float2bfloat16_rn(p2 - __bfloat162float(q2b)),
                             __float2bfloat16_rn(p3 - __bfloat162float(q3b)));
            pal[2] = packbf2(__float2bfloat16_rn(p4 - __bfloat162float(q4b)),
                             __float2bfloat16_rn(p5 - __bfloat162float(q5b)));
            pal[3] = packbf2(__float2bfloat16_rn(p6 - __bfloat162float(q6b)),
                             __float2bfloat16_rn(p7 - __bfloat162float(q7b)));

            const uint32_t koff = ks * 32;
#pragma unroll
            for (int ni = 0; ni < 16; ++ni) {
                uint32_t bh[2], bl[2];
                LDSM2(bh, bVh + ni * (8 * FVP * 2) + koff);
                LDSM2(bl, bVl + ni * (8 * FVP * 2) + koff);
                MMA16816(ao[ni], pah, bh);
                MMA16816(ao[ni], pal, bh);
                MMA16816(ao[ni], pah, bl);
            }
        }
    }

    // ---- epilogue ----
    const float inv0 = 1.0f / l0, inv1 = 1.0f / l1;
    const int r0 = q0 + wrow + (lane >> 2);
    const int ecol = (lane & 3) * 2;
    float* Ob0 = O + ((size_t)(b * L_ + r0) * NH_ + h) * HD_ + ecol;
    float* Ob1 = O + ((size_t)(b * L_ + r0 + 8) * NH_ + h) * HD_ + ecol;
#pragma unroll
    for (int ni = 0; ni < 16; ++ni) {
        *(float2*)(Ob0 + ni * 8) = make_float2(ao[ni][0] * inv0, ao[ni][1] * inv0);
        *(float2*)(Ob1 + ni * 8) = make_float2(ao[ni][2] * inv1, ao[ni][3] * inv1);
    }
}

// ---------------------------------------------------------------------------
extern "C" void kernel_launch(void* const* d_in, const int* in_sizes, int n_in,
                              void* d_out, int out_size) {
    const float* x  = (const float*)d_in[0];
    const float* Wq = (const float*)d_in[1];
    const float* Wk = (const float*)d_in[2];
    const float* Wv = (const float*)d_in[3];
    const float* Wo = (const float*)d_in[4];
    float* out = (float*)d_out;

    float *q, *k, *v, *o;
    cudaGetSymbolAddress((void**)&q, g_q);
    cudaGetSymbolAddress((void**)&k, g_k);
    cudaGetSymbolAddress((void**)&v, g_v);
    cudaGetSymbolAddress((void**)&o, g_o);
    __nv_bfloat16 *xh, *xl, *wqh, *wql, *wkh, *wkl, *wvh, *wvl, *woh, *wol, *oh, *ol;
    cudaGetSymbolAddress((void**)&xh, g_xh);   cudaGetSymbolAddress((void**)&xl, g_xl);
    cudaGetSymbolAddress((void**)&wqh, g_wqh); cudaGetSymbolAddress((void**)&wql, g_wql);
    cudaGetSymbolAddress((void**)&wkh, g_wkh); cudaGetSymbolAddress((void**)&wkl, g_wkl);
    cudaGetSymbolAddress((void**)&wvh, g_wvh); cudaGetSymbolAddress((void**)&wvl, g_wvl);
    cudaGetSymbolAddress((void**)&woh, g_woh); cudaGetSymbolAddress((void**)&wol, g_wol);
    cudaGetSymbolAddress((void**)&oh, g_oh);   cudaGetSymbolAddress((void**)&ol, g_ol);

    const int M = B_ * L_;       // 4096
    const int NKVD = NKV_ * HD_; // 1024

    cudaFuncSetAttribute(gemm_mma, cudaFuncAttributeMaxDynamicSharedMemorySize, GT_SMEM);
    cudaFuncSetAttribute(flash_mma, cudaFuncAttributeMaxDynamicSharedMemorySize, FM_SMEM);

    rope_table_kernel<<<(L_ * 64 + 255) / 256, 256>>>();

    split_bf16<<<(M * D_ / 4 + 255) / 256, 256>>>(x, xh, xl, M * D_ / 4);
    split_bf16<<<(D_ * D_ / 4 + 255) / 256, 256>>>(Wq, wqh, wql, D_ * D_ / 4);
    split_bf16<<<(NKVD * D_ / 4 + 255) / 256, 256>>>(Wk, wkh, wkl, NKVD * D_ / 4);
    split_bf16<<<(NKVD * D_ / 4 + 255) / 256, 256>>>(Wv, wvh, wvl, NKVD * D_ / 4);
    split_bf16<<<(D_ * D_ / 4 + 255) / 256, 256>>>(Wo, woh, wol, D_ * D_ / 4);

    gemm_mma<<<dim3(D_ / 128, M / 128), 256, GT_SMEM>>>(xh, xl, wqh, wql, q, D_, D_);
    gemm_mma<<<dim3(NKVD / 128, M / 128), 256, GT_SMEM>>>(xh, xl, wkh, wkl, k, NKVD, D_);
    gemm_mma<<<dim3(NKVD / 128, M / 128), 256, GT_SMEM>>>(xh, xl, wvh, wvl, v, NKVD, D_);

    {
        const long long total = (long long)B_ * L_ * (NH_ + NKV_) * 64;
        const int blocks = (int)((total + 255) / 256);
        rope_apply_kernel<<<blocks, 256>>>(q, k);
    }

    flash_mma<<<dim3(L_ / 128, NH_, B_), 256, FM_SMEM>>>(q, k, v, o);

    split_bf16<<<(M * D_ / 4 + 255) / 256, 256>>>(o, oh, ol, M * D_ / 4);
    gemm_mma<<<dim3(D_ / 128, M / 128), 256, GT_SMEM>>>(oh, ol, woh, wol, out, D_, D_);
}

// round 8
// speedup vs baseline: 2.2364x; 1.1973x over previous
#include <cuda_runtime.h>
#include <cuda_bf16.h>
#include <math.h>
#include <stdint.h>

#define B_  2
#define L_  2048
#define D_  2048
#define NH_ 16
#define NKV_ 8
#define HD_ 128
#define GQ_ 2
#define SCALE_ 0.08838834764831845f  // 128^-0.5

// ---------------- scratch (static device globals) ----------------
__device__ float g_q[(size_t)B_ * L_ * NH_ * HD_];
__device__ float g_k[(size_t)B_ * L_ * NKV_ * HD_];
__device__ float g_v[(size_t)B_ * L_ * NKV_ * HD_];
__device__ float g_o[(size_t)B_ * L_ * NH_ * HD_];
__device__ float g_cos[(size_t)L_ * 64];
__device__ float g_sin[(size_t)L_ * 64];

__device__ __nv_bfloat16 g_xh[(size_t)B_ * L_ * D_];
__device__ __nv_bfloat16 g_xl[(size_t)B_ * L_ * D_];
__device__ __nv_bfloat16 g_wqh[(size_t)D_ * D_];
__device__ __nv_bfloat16 g_wql[(size_t)D_ * D_];
__device__ __nv_bfloat16 g_wkh[(size_t)NKV_ * HD_ * D_];
__device__ __nv_bfloat16 g_wkl[(size_t)NKV_ * HD_ * D_];
__device__ __nv_bfloat16 g_wvh[(size_t)NKV_ * HD_ * D_];
__device__ __nv_bfloat16 g_wvl[(size_t)NKV_ * HD_ * D_];
__device__ __nv_bfloat16 g_woh[(size_t)D_ * D_];
__device__ __nv_bfloat16 g_wol[(size_t)D_ * D_];
__device__ __nv_bfloat16 g_oh[(size_t)B_ * L_ * D_];
__device__ __nv_bfloat16 g_ol[(size_t)B_ * L_ * D_];

// pre-split (and RoPE'd / transposed) attention operands
__device__ __nv_bfloat16 g_qh[(size_t)B_ * L_ * NH_ * HD_];
__device__ __nv_bfloat16 g_ql[(size_t)B_ * L_ * NH_ * HD_];
__device__ __nv_bfloat16 g_kh[(size_t)B_ * L_ * NKV_ * HD_];
__device__ __nv_bfloat16 g_kl[(size_t)B_ * L_ * NKV_ * HD_];
__device__ __nv_bfloat16 g_vth[(size_t)B_ * NKV_ * HD_ * L_];
__device__ __nv_bfloat16 g_vtl[(size_t)B_ * NKV_ * HD_ * L_];

// ---------------- helpers ----------------
__device__ __forceinline__ uint32_t smem_u32(const void* p) {
    uint32_t a;
    asm("{ .reg .u64 t; cvta.to.shared.u64 t, %1; cvt.u32.u64 %0, t; }"
        : "=r"(a) : "l"(p));
    return a;
}
#define LDSM4(r, a) \
    asm volatile("ldmatrix.sync.aligned.m8n8.x4.shared.b16 {%0,%1,%2,%3}, [%4];" \
                 : "=r"((r)[0]), "=r"((r)[1]), "=r"((r)[2]), "=r"((r)[3]) : "r"(a))
#define LDSM2(r, a) \
    asm volatile("ldmatrix.sync.aligned.m8n8.x2.shared.b16 {%0,%1}, [%2];" \
                 : "=r"((r)[0]), "=r"((r)[1]) : "r"(a))
#define MMA16816(d, a, b) \
    asm volatile("mma.sync.aligned.m16n8k16.row.col.f32.bf16.bf16.f32 " \
                 "{%0,%1,%2,%3}, {%4,%5,%6,%7}, {%8,%9}, {%0,%1,%2,%3};" \
                 : "+f"((d)[0]), "+f"((d)[1]), "+f"((d)[2]), "+f"((d)[3]) \
                 : "r"((a)[0]), "r"((a)[1]), "r"((a)[2]), "r"((a)[3]), \
                   "r"((b)[0]), "r"((b)[1]))
#define CP_ASYNC16(s, g) \
    asm volatile("cp.async.cg.shared.global [%0], [%1], 16;" :: "r"(s), "l"(g))
#define CP_COMMIT() asm volatile("cp.async.commit_group;" ::: "memory")
#define CP_WAIT1()  asm volatile("cp.async.wait_group 1;" ::: "memory")
#define CP_WAIT0()  asm volatile("cp.async.wait_group 0;" ::: "memory")

__device__ __forceinline__ uint32_t packbf2(__nv_bfloat16 lo, __nv_bfloat16 hi) {
    __nv_bfloat162 t = __halves2bfloat162(lo, hi);
    return *(uint32_t*)&t;
}

// ---------------------------------------------------------------------------
// split: fp32 -> bf16 hi + bf16 lo
// ---------------------------------------------------------------------------
__global__ void split_bf16(const float* __restrict__ s,
                           __nv_bfloat16* __restrict__ h,
                           __nv_bfloat16* __restrict__ l, int n4) {
    const int i = blockIdx.x * blockDim.x + threadIdx.x;
    if (i >= n4) return;
    const float4 v = ((const float4*)s)[i];
    __nv_bfloat16 h0 = __float2bfloat16_rn(v.x);
    __nv_bfloat16 h1 = __float2bfloat16_rn(v.y);
    __nv_bfloat16 h2 = __float2bfloat16_rn(v.z);
    __nv_bfloat16 h3 = __float2bfloat16_rn(v.w);
    h[i * 4 + 0] = h0; h[i * 4 + 1] = h1; h[i * 4 + 2] = h2; h[i * 4 + 3] = h3;
    l[i * 4 + 0] = __float2bfloat16_rn(v.x - __bfloat162float(h0));
    l[i * 4 + 1] = __float2bfloat16_rn(v.y - __bfloat162float(h1));
    l[i * 4 + 2] = __float2bfloat16_rn(v.z - __bfloat162float(h2));
    l[i * 4 + 3] = __float2bfloat16_rn(v.w - __bfloat162float(h3));
}

// ---------------------------------------------------------------------------
// mma.sync bf16x3 GEMM (validated)
// ---------------------------------------------------------------------------
#define GP 72
#define GT_TILE (128 * GP)
#define GT_SMEM (4 * GT_TILE * 2)

__global__ void __launch_bounds__(256) gemm_mma(const __nv_bfloat16* __restrict__ Ah,
                                                const __nv_bfloat16* __restrict__ Al,
                                                const __nv_bfloat16* __restrict__ Bh,
                                                const __nv_bfloat16* __restrict__ Bl,
                                                float* __restrict__ C,
                                                int N, int K) {
    extern __shared__ __nv_bfloat16 sb[];
    __nv_bfloat16* Ash = sb;
    __nv_bfloat16* Asl = sb + GT_TILE;
    __nv_bfloat16* Bsh = sb + 2 * GT_TILE;
    __nv_bfloat16* Bsl = sb + 3 * GT_TILE;

    const int tid = threadIdx.x;
    const int lane = tid & 31;
    const int wid = tid >> 5;
    const int wm = (wid >> 2) * 64;
    const int wn = (wid & 3) * 32;
    const int m0 = blockIdx.y * 128;
    const int n0 = blockIdx.x * 128;

    const int srow = tid >> 1;
    const int sub  = (tid & 1) * 4;

    float acc[4][4][4];
#pragma unroll
    for (int i = 0; i < 4; ++i)
#pragma unroll
        for (int j = 0; j < 4; ++j)
#pragma unroll
            for (int q = 0; q < 4; ++q) acc[i][j][q] = 0.f;

    const int arow = lane & 15, acol = (lane >> 4) << 3;
    const int brow = lane & 7,  bcol = ((lane >> 3) & 1) << 3;
    const uint32_t a_h0 = smem_u32(Ash + (wm + arow) * GP + acol);
    const uint32_t a_l0 = smem_u32(Asl + (wm + arow) * GP + acol);
    const uint32_t b_h0 = smem_u32(Bsh + (wn + brow) * GP + bcol);
    const uint32_t b_l0 = smem_u32(Bsl + (wn + brow) * GP + bcol);

    for (int kc = 0; kc < K; kc += 64) {
        {
            const char* gA = (const char*)(Ah + (size_t)(m0 + srow) * K + kc);
            const char* gAl = (const char*)(Al + (size_t)(m0 + srow) * K + kc);
            const char* gB = (const char*)(Bh + (size_t)(n0 + srow) * K + kc);
            const char* gBl = (const char*)(Bl + (size_t)(n0 + srow) * K + kc);
            char* dA  = (char*)(Ash + srow * GP);
            char* dAl = (char*)(Asl + srow * GP);
            char* dB  = (char*)(Bsh + srow * GP);
            char* dBl = (char*)(Bsl + srow * GP);
#pragma unroll
            for (int u = 0; u < 4; ++u) {
                const int off = (sub + u) * 16;
                *(float4*)(dA + off)  = *(const float4*)(gA + off);
                *(float4*)(dAl + off) = *(const float4*)(gAl + off);
                *(float4*)(dB + off)  = *(const float4*)(gB + off);
                *(float4*)(dBl + off) = *(const float4*)(gBl + off);
            }
        }
        __syncthreads();

#pragma unroll
        for (int ks = 0; ks < 4; ++ks) {
            const uint32_t koff = ks * 16 * 2;
            uint32_t ah[4][4], al[4][4], bh[4][2], bl[4][2];
#pragma unroll
            for (int mi = 0; mi < 4; ++mi) {
                LDSM4(ah[mi], a_h0 + mi * 16 * GP * 2 + koff);
                LDSM4(al[mi], a_l0 + mi * 16 * GP * 2 + koff);
            }
#pragma unroll
            for (int ni = 0; ni < 4; ++ni) {
                LDSM2(bh[ni], b_h0 + ni * 8 * GP * 2 + koff);
                LDSM2(bl[ni], b_l0 + ni * 8 * GP * 2 + koff);
            }
#pragma unroll
            for (int mi = 0; mi < 4; ++mi)
#pragma unroll
                for (int ni = 0; ni < 4; ++ni) {
                    MMA16816(acc[mi][ni], ah[mi], bh[ni]);
                    MMA16816(acc[mi][ni], ah[mi], bl[ni]);
                    MMA16816(acc[mi][ni], al[mi], bh[ni]);
                }
        }
        __syncthreads();
    }

    const int erow = lane >> 2;
    const int ecol = (lane & 3) * 2;
#pragma unroll
    for (int mi = 0; mi < 4; ++mi)
#pragma unroll
        for (int ni = 0; ni < 4; ++ni) {
            float* cp = C + (size_t)(m0 + wm + mi * 16 + erow) * N + n0 + wn + ni * 8 + ecol;
            *(float2*)cp = make_float2(acc[mi][ni][0], acc[mi][ni][1]);
            *(float2*)(cp + 8 * (size_t)N) = make_float2(acc[mi][ni][2], acc[mi][ni][3]);
        }
}

// ---------------------------------------------------------------------------
// RoPE table
// ---------------------------------------------------------------------------
__global__ void rope_table_kernel() {
    const int idx = blockIdx.x * blockDim.x + threadIdx.x;
    if (idx >= L_ * 64) return;
    const int i = idx & 63;
    const int pos = idx >> 6;
    const double inv = exp(-(double)i / 64.0 * log(10000.0));
    double sd, cd;
    sincos((double)pos * inv, &sd, &cd);
    g_cos[idx] = (float)cd;
    g_sin[idx] = (float)sd;
}

// ---------------------------------------------------------------------------
// RoPE + bf16 hi/lo split for Q and K (fused, writes split arrays directly)
// ---------------------------------------------------------------------------
__global__ void rope_split_kernel(const float* __restrict__ q,
                                  const float* __restrict__ k,
                                  __nv_bfloat16* __restrict__ qh,
                                  __nv_bfloat16* __restrict__ ql,
                                  __nv_bfloat16* __restrict__ kh,
                                  __nv_bfloat16* __restrict__ kl) {
    const long long idx = (long long)blockIdx.x * blockDim.x + threadIdx.x;
    const long long total = (long long)B_ * L_ * (NH_ + NKV_) * 64;
    if (idx >= total) return;

    const int i  = (int)(idx & 63);
    long long r  = idx >> 6;
    const int hh = (int)(r % (NH_ + NKV_));
    r /= (NH_ + NKV_);
    const int bl  = (int)r;
    const int pos = bl & (L_ - 1);

    const float* src;
    __nv_bfloat16 *dh, *dl;
    size_t off;
    if (hh < NH_) {
        off = ((size_t)bl * NH_ + hh) * HD_;
        src = q + off; dh = qh + off; dl = ql + off;
    } else {
        off = ((size_t)bl * NKV_ + (hh - NH_)) * HD_;
        src = k + off; dh = kh + off; dl = kl + off;
    }

    const float c = g_cos[pos * 64 + i];
    const float s = g_sin[pos * 64 + i];
    const float a = src[i];
    const float b = src[i + 64];
    const float r0 = a * c - b * s;
    const float r1 = b * c + a * s;

    const __nv_bfloat16 h0 = __float2bfloat16_rn(r0);
    const __nv_bfloat16 h1 = __float2bfloat16_rn(r1);
    dh[i]      = h0;
    dh[i + 64] = h1;
    dl[i]      = __float2bfloat16_rn(r0 - __bfloat162float(h0));
    dl[i + 64] = __float2bfloat16_rn(r1 - __bfloat162float(h1));
}

// ---------------------------------------------------------------------------
// V: split + transpose to [b][kvh][d][L] bf16 hi/lo
// ---------------------------------------------------------------------------
__global__ void vt_split_kernel(const float* __restrict__ v,
                                __nv_bfloat16* __restrict__ vth,
                                __nv_bfloat16* __restrict__ vtl) {
    __shared__ float s[32][33];
    const int tx = threadIdx.x, ty = threadIdx.y;   // 32 x 8
    const int l0 = blockIdx.x * 32, d0 = blockIdx.y * 32;
    const int bk = blockIdx.z;                      // b*NKV + kvh
    const int b = bk >> 3, kvh = bk & 7;

    const float* vb = v + ((size_t)b * L_ * NKV_ + kvh) * HD_;
#pragma unroll
    for (int rr = 0; rr < 4; ++rr) {
        const int lr = ty * 4 + rr;
        s[lr][tx] = vb[(size_t)(l0 + lr) * (NKV_ * HD_) + d0 + tx];
    }
    __syncthreads();

    __nv_bfloat16* oh = vth + (size_t)bk * HD_ * L_;
    __nv_bfloat16* ol = vtl + (size_t)bk * HD_ * L_;
#pragma unroll
    for (int rr = 0; rr < 4; ++rr) {
        const int dr = ty * 4 + rr;
        const float val = s[tx][dr];
        const __nv_bfloat16 hv = __float2bfloat16_rn(val);
        oh[(size_t)(d0 + dr) * L_ + l0 + tx] = hv;
        ol[(size_t)(d0 + dr) * L_ + l0 + tx] =
            __float2bfloat16_rn(val - __bfloat162float(hv));
    }
}

// ---------------------------------------------------------------------------
// Flash attention v5: mma.sync + pre-split bf16 operands + cp.async
// double-buffered K/V staging.
// smem: Qh/Ql [128][136]; 2 x { Kh/Kl [64][136], Vth/Vtl [128][72] }
// ---------------------------------------------------------------------------
#define FQP 136
#define FVP 72
#define SQL_OFF   34816
#define SBUF_OFF  69632
#define KVBUF     71680
#define OKH 0
#define OKL 17408
#define OVH 34816
#define OVL 53248
#define FM_SMEM (69632 + 2 * 71680)   // 212992

__device__ __forceinline__ void fm_stage(uint32_t sbuf,
                                         const char* kh, const char* kl,
                                         const char* vth, const char* vtl,
                                         int k0, int tid) {
    // K tile: 64 rows x 256B (pitch 272)
    for (int i = tid; i < 64 * 16; i += 256) {
        const int row = i >> 4;
        const int u = (i & 15) << 4;
        const size_t g = (size_t)(k0 + row) * (NKV_ * HD_ * 2) + u;
        const uint32_t d = sbuf + row * 272 + u;
        CP_ASYNC16(d + OKH, kh + g);
        CP_ASYNC16(d + OKL, kl + g);
    }
    // V^T tile: 128 rows x 128B (pitch 144)
    for (int i = tid; i < 128 * 8; i += 256) {
        const int row = i >> 3;
        const int u = (i & 7) << 4;
        const size_t g = (size_t)row * (L_ * 2) + (size_t)k0 * 2 + u;
        const uint32_t d = sbuf + row * 144 + u;
        CP_ASYNC16(d + OVH, vth + g);
        CP_ASYNC16(d + OVL, vtl + g);
    }
}

__global__ void __launch_bounds__(256) flash_mma(const __nv_bfloat16* __restrict__ Qhg,
                                                 const __nv_bfloat16* __restrict__ Qlg,
                                                 const __nv_bfloat16* __restrict__ Khg,
                                                 const __nv_bfloat16* __restrict__ Klg,
                                                 const __nv_bfloat16* __restrict__ Vthg,
                                                 const __nv_bfloat16* __restrict__ Vtlg,
                                                 float* __restrict__ O) {
    extern __shared__ char smem[];
    const uint32_t sQh = smem_u32(smem);
    const uint32_t sQl = sQh + SQL_OFF;
    const uint32_t sB0 = sQh + SBUF_OFF;

    const int tid = threadIdx.x;
    const int lane = tid & 31, wid = tid >> 5;
    const int b = blockIdx.z, h = blockIdx.y;
    const int kvh = h >> 1;
    const int qt = (gridDim.x - 1) - blockIdx.x;   // heavy tiles first
    const int q0 = qt * 128;
    const int wrow = wid * 16;

    const char* qh_g = (const char*)(Qhg + ((size_t)(b * L_ + q0) * NH_ + h) * HD_);
    const char* ql_g = (const char*)(Qlg + ((size_t)(b * L_ + q0) * NH_ + h) * HD_);
    const char* kh_g = (const char*)(Khg + ((size_t)b * L_ * NKV_ + kvh) * HD_);
    const char* kl_g = (const char*)(Klg + ((size_t)b * L_ * NKV_ + kvh) * HD_);
    const char* vth_g = (const char*)(Vthg + (size_t)(b * NKV_ + kvh) * HD_ * L_);
    const char* vtl_g = (const char*)(Vtlg + (size_t)(b * NKV_ + kvh) * HD_ * L_);

    // stage Q (once) + first K/V tile, one commit group
    for (int i = tid; i < 128 * 16; i += 256) {
        const int row = i >> 4;
        const int u = (i & 15) << 4;
        const size_t g = (size_t)row * (NH_ * HD_ * 2) + u;
        const uint32_t d = row * 272 + u;
        CP_ASYNC16(sQh + d, qh_g + g);
        CP_ASYNC16(sQl + d, ql_g + g);
    }
    fm_stage(sB0, kh_g, kl_g, vth_g, vtl_g, 0, tid);
    CP_COMMIT();

    // fragment smem addresses
    const uint32_t aQh = sQh + (wrow + (lane & 15)) * 272 + ((lane >> 4) << 4);
    const uint32_t aQl = aQh + SQL_OFF;
    const uint32_t bK0 = sB0 + (lane & 7) * 272 + (((lane >> 3) & 1) << 4);
    const uint32_t bV0 = sB0 + OVH + (lane & 7) * 144 + (((lane >> 3) & 1) << 4);

    float m0 = -1e30f, m1 = -1e30f, l0 = 0.f, l1 = 0.f;
    float ao[16][4];
#pragma unroll
    for (int i = 0; i < 16; ++i)
#pragma unroll
        for (int j = 0; j < 4; ++j) ao[i][j] = 0.f;

    const int tmax = 2 * qt + 2;
    for (int t = 0; t < tmax; ++t) {
        const int k0 = t * 64;
        const uint32_t boff = (uint32_t)(t & 1) * KVBUF;

        if (t + 1 < tmax) {
            fm_stage(sB0 + (uint32_t)((t + 1) & 1) * KVBUF,
                     kh_g, kl_g, vth_g, vtl_g, k0 + 64, tid);
            CP_COMMIT();
            CP_WAIT1();
        } else {
            CP_WAIT0();
        }
        __syncthreads();

        const uint32_t bKh = bK0 + boff;
        const uint32_t bKl = bKh + OKL;
        const uint32_t bVh = bV0 + boff;
        const uint32_t bVl = bVh + (OVL - OVH);

        // ---- S = Q @ K^T (3-way split) ----
        float sc[8][4];
#pragma unroll
        for (int ni = 0; ni < 8; ++ni)
#pragma unroll
            for (int j = 0; j < 4; ++j) sc[ni][j] = 0.f;

#pragma unroll
        for (int ks = 0; ks < 8; ++ks) {
            const uint32_t koff = ks * 32;
            uint32_t ah[4], al[4];
            LDSM4(ah, aQh + koff);
            LDSM4(al, aQl + koff);
#pragma unroll
            for (int ni = 0; ni < 8; ++ni) {
                uint32_t bh[2], bl[2];
                LDSM2(bh, bKh + ni * (8 * 272) + koff);
                LDSM2(bl, bKl + ni * (8 * 272) + koff);
                MMA16816(sc[ni], ah, bh);
                MMA16816(sc[ni], ah, bl);
                MMA16816(sc[ni], al, bh);
            }
        }

#pragma unroll
        for (int ni = 0; ni < 8; ++ni)
#pragma unroll
            for (int j = 0; j < 4; ++j) sc[ni][j] *= SCALE_;

        if (t >= tmax - 2) {
            const int qr0 = q0 + wrow + (lane >> 2);
#pragma unroll
            for (int ni = 0; ni < 8; ++ni) {
                const int kc = k0 + ni * 8 + (lane & 3) * 2;
                if (kc > qr0)         sc[ni][0] = -1e30f;
                if (kc + 1 > qr0)     sc[ni][1] = -1e30f;
                if (kc > qr0 + 8)     sc[ni][2] = -1e30f;
                if (kc + 1 > qr0 + 8) sc[ni][3] = -1e30f;
            }
        }

        // ---- online softmax ----
        float mx0 = -1e30f, mx1 = -1e30f;
#pragma unroll
        for (int ni = 0; ni < 8; ++ni) {
            mx0 = fmaxf(mx0, fmaxf(sc[ni][0], sc[ni][1]));
            mx1 = fmaxf(mx1, fmaxf(sc[ni][2], sc[ni][3]));
        }
        mx0 = fmaxf(mx0, __shfl_xor_sync(0xffffffffu, mx0, 1));
        mx0 = fmaxf(mx0, __shfl_xor_sync(0xffffffffu, mx0, 2));
        mx1 = fmaxf(mx1, __shfl_xor_sync(0xffffffffu, mx1, 1));
        mx1 = fmaxf(mx1, __shfl_xor_sync(0xffffffffu, mx1, 2));

        const float nm0 = fmaxf(m0, mx0), nm1 = fmaxf(m1, mx1);
        const float al0 = __expf(m0 - nm0), al1 = __expf(m1 - nm1);
        float s0 = 0.f, s1 = 0.f;
#pragma unroll
        for (int ni = 0; ni < 8; ++ni) {
            sc[ni][0] = __expf(sc[ni][0] - nm0); s0 += sc[ni][0];
            sc[ni][1] = __expf(sc[ni][1] - nm0); s0 += sc[ni][1];
            sc[ni][2] = __expf(sc[ni][2] - nm1); s1 += sc[ni][2];
            sc[ni][3] = __expf(sc[ni][3] - nm1); s1 += sc[ni][3];
        }
        s0 += __shfl_xor_sync(0xffffffffu, s0, 1);
        s0 += __shfl_xor_sync(0xffffffffu, s0, 2);
        s1 += __shfl_xor_sync(0xffffffffu, s1, 1);
        s1 += __shfl_xor_sync(0xffffffffu, s1, 2);
        l0 = l0 * al0 + s0; l1 = l1 * al1 + s1;
        m0 = nm0; m1 = nm1;

#pragma unroll
        for (int i = 0; i < 16; ++i) {
            ao[i][0] *= al0; ao[i][1] *= al0;
            ao[i][2] *= al1; ao[i][3] *= al1;
        }

        // ---- O += P @ V ----
#pragma unroll
        for (int ks = 0; ks < 4; ++ks) {
            const float p0 = sc[2 * ks][0], p1 = sc[2 * ks][1];
            const float p2 = sc[2 * ks][2], p3 = sc[2 * ks][3];
            const float p4 = sc[2 * ks + 1][0], p5 = sc[2 * ks + 1][1];
            const float p6 = sc[2 * ks + 1][2], p7 = sc[2 * ks + 1][3];
            const __nv_bfloat16 q0b = __float2bfloat16_rn(p0), q1b = __float2bfloat16_rn(p1);
            const __nv_bfloat16 q2b = __float2bfloat16_rn(p2), q3b = __float2bfloat16_rn(p3);
            const __nv_bfloat16 q4b = __float2bfloat16_rn(p4), q5b = __float2bfloat16_rn(p5);
            const __nv_bfloat16 q6b = __float2bfloat16_rn(p6), q7b = __float2bfloat16_rn(p7);
            uint32_t pah[4], pal[4];
            pah[0] = packbf2(q0b, q1b);
            pah[1] = packbf2(q2b, q3b);
            pah[2] = packbf2(q4b, q5b);
            pah[3] = packbf2(q6b, q7b);
            pal[0] = packbf2(__float2bfloat16_rn(p0 - __bfloat162float(q0b)),
                             __float2bfloat16_rn(p1 - __bfloat162float(q1b)));
            pal[1] = packbf2(__float2bfloat16_rn(p2 - __bfloat162float(q2b)),
                             __float2bfloat16_rn(p3 - __bfloat162float(q3b)));
            pal[2] = packbf2(__float2bfloat16_rn(p4 - __bfloat162float(q4b)),
                             __float2bfloat16_rn(p5 - __bfloat162float(q5b)));
            pal[3] = packbf2(__float2bfloat16_rn(p6 - __bfloat162float(q6b)),
                             __float2bfloat16_rn(p7 - __bfloat162float(q7b)));

            const uint32_t koff = ks * 32;
#pragma unroll
            for (int ni = 0; ni < 16; ++ni) {
                uint32_t bh[2], bl[2];
                LDSM2(bh, bVh + ni * (8 * 144) + koff);
                LDSM2(bl, bVl + ni * (8 * 144) + koff);
                MMA16816(ao[ni], pah, bh);
                MMA16816(ao[ni], pal, bh);
                MMA16816(ao[ni], pah, bl);
            }
        }
        __syncthreads();   // compute done before this buffer is restaged
    }

    // ---- epilogue ----
    const float inv0 = 1.0f / l0, inv1 = 1.0f / l1;
    const int r0 = q0 + wrow + (lane >> 2);
    const int ecol = (lane & 3) * 2;
    float* Ob0 = O + ((size_t)(b * L_ + r0) * NH_ + h) * HD_ + ecol;
    float* Ob1 = O + ((size_t)(b * L_ + r0 + 8) * NH_ + h) * HD_ + ecol;
#pragma unroll
    for (int ni = 0; ni < 16; ++ni) {
        *(float2*)(Ob0 + ni * 8) = make_float2(ao[ni][0] * inv0, ao[ni][1] * inv0);
        *(float2*)(Ob1 + ni * 8) = make_float2(ao[ni][2] * inv1, ao[ni][3] * inv1);
    }
}

// ---------------------------------------------------------------------------
extern "C" void kernel_launch(void* const* d_in, const int* in_sizes, int n_in,
                              void* d_out, int out_size) {
    const float* x  = (const float*)d_in[0];
    const float* Wq = (const float*)d_in[1];
    const float* Wk = (const float*)d_in[2];
    const float* Wv = (const float*)d_in[3];
    const float* Wo = (const float*)d_in[4];
    float* out = (float*)d_out;

    float *q, *k, *v, *o;
    cudaGetSymbolAddress((void**)&q, g_q);
    cudaGetSymbolAddress((void**)&k, g_k);
    cudaGetSymbolAddress((void**)&v, g_v);
    cudaGetSymbolAddress((void**)&o, g_o);
    __nv_bfloat16 *xh, *xl, *wqh, *wql, *wkh, *wkl, *wvh, *wvl, *woh, *wol, *oh, *ol;
    __nv_bfloat16 *qh, *ql, *kh, *kl, *vth, *vtl;
    cudaGetSymbolAddress((void**)&xh, g_xh);   cudaGetSymbolAddress((void**)&xl, g_xl);
    cudaGetSymbolAddress((void**)&wqh, g_wqh); cudaGetSymbolAddress((void**)&wql, g_wql);
    cudaGetSymbolAddress((void**)&wkh, g_wkh); cudaGetSymbolAddress((void**)&wkl, g_wkl);
    cudaGetSymbolAddress((void**)&wvh, g_wvh); cudaGetSymbolAddress((void**)&wvl, g_wvl);
    cudaGetSymbolAddress((void**)&woh, g_woh); cudaGetSymbolAddress((void**)&wol, g_wol);
    cudaGetSymbolAddress((void**)&oh, g_oh);   cudaGetSymbolAddress((void**)&ol, g_ol);
    cudaGetSymbolAddress((void**)&qh, g_qh);   cudaGetSymbolAddress((void**)&ql, g_ql);
    cudaGetSymbolAddress((void**)&kh, g_kh);   cudaGetSymbolAddress((void**)&kl, g_kl);
    cudaGetSymbolAddress((void**)&vth, g_vth); cudaGetSymbolAddress((void**)&vtl, g_vtl);

    const int M = B_ * L_;       // 4096
    const int NKVD = NKV_ * HD_; // 1024

    cudaFuncSetAttribute(gemm_mma, cudaFuncAttributeMaxDynamicSharedMemorySize, GT_SMEM);
    cudaFuncSetAttribute(flash_mma, cudaFuncAttributeMaxDynamicSharedMemorySize, FM_SMEM);

    rope_table_kernel<<<(L_ * 64 + 255) / 256, 256>>>();

    split_bf16<<<(M * D_ / 4 + 255) / 256, 256>>>(x, xh, xl, M * D_ / 4);
    split_bf16<<<(D_ * D_ / 4 + 255) / 256, 256>>>(Wq, wqh, wql, D_ * D_ / 4);
    split_bf16<<<(NKVD * D_ / 4 + 255) / 256, 256>>>(Wk, wkh, wkl, NKVD * D_ / 4);
    split_bf16<<<(NKVD * D_ / 4 + 255) / 256, 256>>>(Wv, wvh, wvl, NKVD * D_ / 4);
    split_bf16<<<(D_ * D_ / 4 + 255) / 256, 256>>>(Wo, woh, wol, D_ * D_ / 4);

    gemm_mma<<<dim3(D_ / 128, M / 128), 256, GT_SMEM>>>(xh, xl, wqh, wql, q, D_, D_);
    gemm_mma<<<dim3(NKVD / 128, M / 128), 256, GT_SMEM>>>(xh, xl, wkh, wkl, k, NKVD, D_);
    gemm_mma<<<dim3(NKVD / 128, M / 128), 256, GT_SMEM>>>(xh, xl, wvh, wvl, v, NKVD, D_);

    {
        const long long total = (long long)B_ * L_ * (NH_ + NKV_) * 64;
        const int blocks = (int)((total + 255) / 256);
        rope_split_kernel<<<blocks, 256>>>(q, k, qh, ql, kh, kl);
    }
    vt_split_kernel<<<dim3(L_ / 32, HD_ / 32, B_ * NKV_), dim3(32, 8)>>>(v, vth, vtl);

    flash_mma<<<dim3(L_ / 128, NH_, B_), 256, FM_SMEM>>>(qh, ql, kh, kl, vth, vtl, o);

    split_bf16<<<(M * D_ / 4 + 255) / 256, 256>>>(o, oh, ol, M * D_ / 4);
    gemm_mma<<<dim3(D_ / 128, M / 128), 256, GT_SMEM>>>(oh, ol, woh, wol, out, D_, D_);
}

// round 10
// speedup vs baseline: 2.3625x; 1.0564x over previous
#include <cuda_runtime.h>
#include <cuda_bf16.h>
#include <math.h>
#include <stdint.h>

#define B_  2
#define L_  2048
#define D_  2048
#define NH_ 16
#define NKV_ 8
#define HD_ 128
#define GQ_ 2
#define SCALE_ 0.08838834764831845f  // 128^-0.5

// ---------------- scratch (static device globals) ----------------
__device__ float g_q[(size_t)B_ * L_ * NH_ * HD_];
__device__ float g_k[(size_t)B_ * L_ * NKV_ * HD_];
__device__ float g_v[(size_t)B_ * L_ * NKV_ * HD_];
__device__ float g_o[(size_t)B_ * L_ * NH_ * HD_];
__device__ float g_cos[(size_t)L_ * 64];
__device__ float g_sin[(size_t)L_ * 64];

__device__ __nv_bfloat16 g_xh[(size_t)B_ * L_ * D_];
__device__ __nv_bfloat16 g_xl[(size_t)B_ * L_ * D_];
__device__ __nv_bfloat16 g_wqh[(size_t)D_ * D_];
__device__ __nv_bfloat16 g_wql[(size_t)D_ * D_];
__device__ __nv_bfloat16 g_wkh[(size_t)NKV_ * HD_ * D_];
__device__ __nv_bfloat16 g_wkl[(size_t)NKV_ * HD_ * D_];
__device__ __nv_bfloat16 g_wvh[(size_t)NKV_ * HD_ * D_];
__device__ __nv_bfloat16 g_wvl[(size_t)NKV_ * HD_ * D_];
__device__ __nv_bfloat16 g_woh[(size_t)D_ * D_];
__device__ __nv_bfloat16 g_wol[(size_t)D_ * D_];
__device__ __nv_bfloat16 g_oh[(size_t)B_ * L_ * D_];
__device__ __nv_bfloat16 g_ol[(size_t)B_ * L_ * D_];

// pre-split (and RoPE'd / transposed) attention operands
__device__ __nv_bfloat16 g_qh[(size_t)B_ * L_ * NH_ * HD_];
__device__ __nv_bfloat16 g_ql[(size_t)B_ * L_ * NH_ * HD_];
__device__ __nv_bfloat16 g_kh[(size_t)B_ * L_ * NKV_ * HD_];
__device__ __nv_bfloat16 g_kl[(size_t)B_ * L_ * NKV_ * HD_];
__device__ __nv_bfloat16 g_vth[(size_t)B_ * NKV_ * HD_ * L_];
__device__ __nv_bfloat16 g_vtl[(size_t)B_ * NKV_ * HD_ * L_];

// ---------------- helpers ----------------
__device__ __forceinline__ uint32_t smem_u32(const void* p) {
    uint32_t a;
    asm("{ .reg .u64 t; cvta.to.shared.u64 t, %1; cvt.u32.u64 %0, t; }"
        : "=r"(a) : "l"(p));
    return a;
}
#define LDSM4(r, a) \
    asm volatile("ldmatrix.sync.aligned.m8n8.x4.shared.b16 {%0,%1,%2,%3}, [%4];" \
                 : "=r"((r)[0]), "=r"((r)[1]), "=r"((r)[2]), "=r"((r)[3]) : "r"(a))
#define LDSM2(r, a) \
    asm volatile("ldmatrix.sync.aligned.m8n8.x2.shared.b16 {%0,%1}, [%2];" \
                 : "=r"((r)[0]), "=r"((r)[1]) : "r"(a))
#define MMA16816(d, a, b) \
    asm volatile("mma.sync.aligned.m16n8k16.row.col.f32.bf16.bf16.f32 " \
                 "{%0,%1,%2,%3}, {%4,%5,%6,%7}, {%8,%9}, {%0,%1,%2,%3};" \
                 : "+f"((d)[0]), "+f"((d)[1]), "+f"((d)[2]), "+f"((d)[3]) \
                 : "r"((a)[0]), "r"((a)[1]), "r"((a)[2]), "r"((a)[3]), \
                   "r"((b)[0]), "r"((b)[1]))
#define CP_ASYNC16(s, g) \
    asm volatile("cp.async.cg.shared.global [%0], [%1], 16;" :: "r"(s), "l"(g))
#define CP_COMMIT() asm volatile("cp.async.commit_group;" ::: "memory")
#define CP_WAIT0()  asm volatile("cp.async.wait_group 0;" ::: "memory")

__device__ __forceinline__ uint32_t packbf2(__nv_bfloat16 lo, __nv_bfloat16 hi) {
    __nv_bfloat162 t = __halves2bfloat162(lo, hi);
    return *(uint32_t*)&t;
}

// ---------------------------------------------------------------------------
// split: fp32 -> bf16 hi + bf16 lo
// ---------------------------------------------------------------------------
__global__ void split_bf16(const float* __restrict__ s,
                           __nv_bfloat16* __restrict__ h,
                           __nv_bfloat16* __restrict__ l, int n4) {
    const int i = blockIdx.x * blockDim.x + threadIdx.x;
    if (i >= n4) return;
    const float4 v = ((const float4*)s)[i];
    __nv_bfloat16 h0 = __float2bfloat16_rn(v.x);
    __nv_bfloat16 h1 = __float2bfloat16_rn(v.y);
    __nv_bfloat16 h2 = __float2bfloat16_rn(v.z);
    __nv_bfloat16 h3 = __float2bfloat16_rn(v.w);
    h[i * 4 + 0] = h0; h[i * 4 + 1] = h1; h[i * 4 + 2] = h2; h[i * 4 + 3] = h3;
    l[i * 4 + 0] = __float2bfloat16_rn(v.x - __bfloat162float(h0));
    l[i * 4 + 1] = __float2bfloat16_rn(v.y - __bfloat162float(h1));
    l[i * 4 + 2] = __float2bfloat16_rn(v.z - __bfloat162float(h2));
    l[i * 4 + 3] = __float2bfloat16_rn(v.w - __bfloat162float(h3));
}

// ---------------------------------------------------------------------------
// mma.sync bf16x3 GEMM (validated)
// ---------------------------------------------------------------------------
#define GP 72
#define GT_TILE (128 * GP)
#define GT_SMEM (4 * GT_TILE * 2)

__global__ void __launch_bounds__(256) gemm_mma(const __nv_bfloat16* __restrict__ Ah,
                                                const __nv_bfloat16* __restrict__ Al,
                                                const __nv_bfloat16* __restrict__ Bh,
                                                const __nv_bfloat16* __restrict__ Bl,
                                                float* __restrict__ C,
                                                int N, int K) {
    extern __shared__ __nv_bfloat16 sb[];
    __nv_bfloat16* Ash = sb;
    __nv_bfloat16* Asl = sb + GT_TILE;
    __nv_bfloat16* Bsh = sb + 2 * GT_TILE;
    __nv_bfloat16* Bsl = sb + 3 * GT_TILE;

    const int tid = threadIdx.x;
    const int lane = tid & 31;
    const int wid = tid >> 5;
    const int wm = (wid >> 2) * 64;
    const int wn = (wid & 3) * 32;
    const int m0 = blockIdx.y * 128;
    const int n0 = blockIdx.x * 128;

    const int srow = tid >> 1;
    const int sub  = (tid & 1) * 4;

    float acc[4][4][4];
#pragma unroll
    for (int i = 0; i < 4; ++i)
#pragma unroll
        for (int j = 0; j < 4; ++j)
#pragma unroll
            for (int q = 0; q < 4; ++q) acc[i][j][q] = 0.f;

    const int arow = lane & 15, acol = (lane >> 4) << 3;
    const int brow = lane & 7,  bcol = ((lane >> 3) & 1) << 3;
    const uint32_t a_h0 = smem_u32(Ash + (wm + arow) * GP + acol);
    const uint32_t a_l0 = smem_u32(Asl + (wm + arow) * GP + acol);
    const uint32_t b_h0 = smem_u32(Bsh + (wn + brow) * GP + bcol);
    const uint32_t b_l0 = smem_u32(Bsl + (wn + brow) * GP + bcol);

    for (int kc = 0; kc < K; kc += 64) {
        {
            const char* gA = (const char*)(Ah + (size_t)(m0 + srow) * K + kc);
            const char* gAl = (const char*)(Al + (size_t)(m0 + srow) * K + kc);
            const char* gB = (const char*)(Bh + (size_t)(n0 + srow) * K + kc);
            const char* gBl = (const char*)(Bl + (size_t)(n0 + srow) * K + kc);
            char* dA  = (char*)(Ash + srow * GP);
            char* dAl = (char*)(Asl + srow * GP);
            char* dB  = (char*)(Bsh + srow * GP);
            char* dBl = (char*)(Bsl + srow * GP);
#pragma unroll
            for (int u = 0; u < 4; ++u) {
                const int off = (sub + u) * 16;
                *(float4*)(dA + off)  = *(const float4*)(gA + off);
                *(float4*)(dAl + off) = *(const float4*)(gAl + off);
                *(float4*)(dB + off)  = *(const float4*)(gB + off);
                *(float4*)(dBl + off) = *(const float4*)(gBl + off);
            }
        }
        __syncthreads();

#pragma unroll
        for (int ks = 0; ks < 4; ++ks) {
            const uint32_t koff = ks * 16 * 2;
            uint32_t ah[4][4], al[4][4], bh[4][2], bl[4][2];
#pragma unroll
            for (int mi = 0; mi < 4; ++mi) {
                LDSM4(ah[mi], a_h0 + mi * 16 * GP * 2 + koff);
                LDSM4(al[mi], a_l0 + mi * 16 * GP * 2 + koff);
            }
#pragma unroll
            for (int ni = 0; ni < 4; ++ni) {
                LDSM2(bh[ni], b_h0 + ni * 8 * GP * 2 + koff);
                LDSM2(bl[ni], b_l0 + ni * 8 * GP * 2 + koff);
            }
#pragma unroll
            for (int mi = 0; mi < 4; ++mi)
#pragma unroll
                for (int ni = 0; ni < 4; ++ni) {
                    MMA16816(acc[mi][ni], ah[mi], bh[ni]);
                    MMA16816(acc[mi][ni], ah[mi], bl[ni]);
                    MMA16816(acc[mi][ni], al[mi], bh[ni]);
                }
        }
        __syncthreads();
    }

    const int erow = lane >> 2;
    const int ecol = (lane & 3) * 2;
#pragma unroll
    for (int mi = 0; mi < 4; ++mi)
#pragma unroll
        for (int ni = 0; ni < 4; ++ni) {
            float* cp = C + (size_t)(m0 + wm + mi * 16 + erow) * N + n0 + wn + ni * 8 + ecol;
            *(float2*)cp = make_float2(acc[mi][ni][0], acc[mi][ni][1]);
            *(float2*)(cp + 8 * (size_t)N) = make_float2(acc[mi][ni][2], acc[mi][ni][3]);
        }
}

// ---------------------------------------------------------------------------
// RoPE table
// ---------------------------------------------------------------------------
__global__ void rope_table_kernel() {
    const int idx = blockIdx.x * blockDim.x + threadIdx.x;
    if (idx >= L_ * 64) return;
    const int i = idx & 63;
    const int pos = idx >> 6;
    const double inv = exp(-(double)i / 64.0 * log(10000.0));
    double sd, cd;
    sincos((double)pos * inv, &sd, &cd);
    g_cos[idx] = (float)cd;
    g_sin[idx] = (float)sd;
}

// ---------------------------------------------------------------------------
// RoPE + bf16 hi/lo split for Q and K
// ---------------------------------------------------------------------------
__global__ void rope_split_kernel(const float* __restrict__ q,
                                  const float* __restrict__ k,
                                  __nv_bfloat16* __restrict__ qh,
                                  __nv_bfloat16* __restrict__ ql,
                                  __nv_bfloat16* __restrict__ kh,
                                  __nv_bfloat16* __restrict__ kl) {
    const long long idx = (long long)blockIdx.x * blockDim.x + threadIdx.x;
    const long long total = (long long)B_ * L_ * (NH_ + NKV_) * 64;
    if (idx >= total) return;

    const int i  = (int)(idx & 63);
    long long r  = idx >> 6;
    const int hh = (int)(r % (NH_ + NKV_));
    r /= (NH_ + NKV_);
    const int bl  = (int)r;
    const int pos = bl & (L_ - 1);

    const float* src;
    __nv_bfloat16 *dh, *dl;
    size_t off;
    if (hh < NH_) {
        off = ((size_t)bl * NH_ + hh) * HD_;
        src = q + off; dh = qh + off; dl = ql + off;
    } else {
        off = ((size_t)bl * NKV_ + (hh - NH_)) * HD_;
        src = k + off; dh = kh + off; dl = kl + off;
    }

    const float c = g_cos[pos * 64 + i];
    const float s = g_sin[pos * 64 + i];
    const float a = src[i];
    const float b = src[i + 64];
    const float r0 = a * c - b * s;
    const float r1 = b * c + a * s;

    const __nv_bfloat16 h0 = __float2bfloat16_rn(r0);
    const __nv_bfloat16 h1 = __float2bfloat16_rn(r1);
    dh[i]      = h0;
    dh[i + 64] = h1;
    dl[i]      = __float2bfloat16_rn(r0 - __bfloat162float(h0));
    dl[i + 64] = __float2bfloat16_rn(r1 - __bfloat162float(h1));
}

// ---------------------------------------------------------------------------
// V: split + transpose to [b][kvh][d][L] bf16 hi/lo
// ---------------------------------------------------------------------------
__global__ void vt_split_kernel(const float* __restrict__ v,
                                __nv_bfloat16* __restrict__ vth,
                                __nv_bfloat16* __restrict__ vtl) {
    __shared__ float s[32][33];
    const int tx = threadIdx.x, ty = threadIdx.y;   // 32 x 8
    const int l0 = blockIdx.x * 32, d0 = blockIdx.y * 32;
    const int bk = blockIdx.z;                      // b*NKV + kvh
    const int b = bk >> 3, kvh = bk & 7;

    const float* vb = v + ((size_t)b * L_ * NKV_ + kvh) * HD_;
#pragma unroll
    for (int rr = 0; rr < 4; ++rr) {
        const int lr = ty * 4 + rr;
        s[lr][tx] = vb[(size_t)(l0 + lr) * (NKV_ * HD_) + d0 + tx];
    }
    __syncthreads();

    __nv_bfloat16* oh = vth + (size_t)bk * HD_ * L_;
    __nv_bfloat16* ol = vtl + (size_t)bk * HD_ * L_;
#pragma unroll
    for (int rr = 0; rr < 4; ++rr) {
        const int dr = ty * 4 + rr;
        const float val = s[tx][dr];
        const __nv_bfloat16 hv = __float2bfloat16_rn(val);
        oh[(size_t)(d0 + dr) * L_ + l0 + tx] = hv;
        ol[(size_t)(d0 + dr) * L_ + l0 + tx] =
            __float2bfloat16_rn(val - __bfloat162float(hv));
    }
}

// ---------------------------------------------------------------------------
// Flash attention v7: 128-thread CTA (64 q-rows), single K/V buffer,
// 104KB smem -> 2 CTAs/SM. Full 3-product splits (S and PV, validated R7 math).
// smem: Qh [64][272B], Ql, Kh [64][272B], Kl, Vth [128 d][144B], Vtl
// ---------------------------------------------------------------------------
#define OQH 0
#define OQL 17408
#define OKH2 34816
#define OKL2 52224
#define OVH2 69632
#define OVL2 88064
#define FM_SMEM 106496

__global__ void __launch_bounds__(128) flash_mma(const __nv_bfloat16* __restrict__ Qhg,
                                                 const __nv_bfloat16* __restrict__ Qlg,
                                                 const __nv_bfloat16* __restrict__ Khg,
                                                 const __nv_bfloat16* __restrict__ Klg,
                                                 const __nv_bfloat16* __restrict__ Vthg,
                                                 const __nv_bfloat16* __restrict__ Vtlg,
                                                 float* __restrict__ O) {
    extern __shared__ char smem[];
    const uint32_t sQ = smem_u32(smem);

    const int tid = threadIdx.x;
    const int lane = tid & 31, wid = tid >> 5;   // 4 warps
    const int b = blockIdx.z, h = blockIdx.y;
    const int kvh = h >> 1;
    const int qt = (gridDim.x - 1) - blockIdx.x;   // heavy tiles first
    const int q0 = qt * 64;
    const int wrow = wid * 16;

    const char* qh_g = (const char*)(Qhg + ((size_t)(b * L_ + q0) * NH_ + h) * HD_);
    const char* ql_g = (const char*)(Qlg + ((size_t)(b * L_ + q0) * NH_ + h) * HD_);
    const char* kh_g = (const char*)(Khg + ((size_t)b * L_ * NKV_ + kvh) * HD_);
    const char* kl_g = (const char*)(Klg + ((size_t)b * L_ * NKV_ + kvh) * HD_);
    const char* vth_g = (const char*)(Vthg + (size_t)(b * NKV_ + kvh) * HD_ * L_);
    const char* vtl_g = (const char*)(Vtlg + (size_t)(b * NKV_ + kvh) * HD_ * L_);

    // stage Q once (joins first tile's wait)
    for (int i = tid; i < 64 * 16; i += 128) {
        const int row = i >> 4;
        const int u = (i & 15) << 4;
        const size_t g = (size_t)row * (NH_ * HD_ * 2) + u;
        const uint32_t d = row * 272 + u;
        CP_ASYNC16(sQ + OQH + d, qh_g + g);
        CP_ASYNC16(sQ + OQL + d, ql_g + g);
    }

    // fragment smem addresses
    const uint32_t aQh = sQ + OQH + (wrow + (lane & 15)) * 272 + ((lane >> 4) << 4);
    const uint32_t aQl = aQh + (OQL - OQH);
    const uint32_t bKh = sQ + OKH2 + (lane & 7) * 272 + (((lane >> 3) & 1) << 4);
    const uint32_t bKl = bKh + (OKL2 - OKH2);
    const uint32_t bVh = sQ + OVH2 + (lane & 7) * 144 + (((lane >> 3) & 1) << 4);
    const uint32_t bVl = bVh + (OVL2 - OVH2);

    float m0 = -1e30f, m1 = -1e30f, l0 = 0.f, l1 = 0.f;
    float ao[16][4];
#pragma unroll
    for (int i = 0; i < 16; ++i)
#pragma unroll
        for (int j = 0; j < 4; ++j) ao[i][j] = 0.f;

    for (int t = 0; t <= qt; ++t) {
        const int k0 = t * 64;

        // ---- stage K (h/l) + V^T (h/l) for this tile ----
        for (int i = tid; i < 64 * 16; i += 128) {
            const int row = i >> 4;
            const int u = (i & 15) << 4;
            const size_t g = (size_t)(k0 + row) * (NKV_ * HD_ * 2) + u;
            const uint32_t d = row * 272 + u;
            CP_ASYNC16(sQ + OKH2 + d, kh_g + g);
            CP_ASYNC16(sQ + OKL2 + d, kl_g + g);
        }
        for (int i = tid; i < 128 * 8; i += 128) {
            const int row = i >> 3;
            const int u = (i & 7) << 4;
            const size_t g = (size_t)row * (L_ * 2) + (size_t)k0 * 2 + u;
            const uint32_t d = row * 144 + u;
            CP_ASYNC16(sQ + OVH2 + d, vth_g + g);
            CP_ASYNC16(sQ + OVL2 + d, vtl_g + g);
        }
        CP_COMMIT();
        CP_WAIT0();
        __syncthreads();

        // ---- S = Q @ K^T (3-way split) ----
        float sc[8][4];
#pragma unroll
        for (int ni = 0; ni < 8; ++ni)
#pragma unroll
            for (int j = 0; j < 4; ++j) sc[ni][j] = 0.f;

#pragma unroll
        for (int ks = 0; ks < 8; ++ks) {
            const uint32_t koff = ks * 32;
            uint32_t ah[4], al[4];
            LDSM4(ah, aQh + koff);
            LDSM4(al, aQl + koff);
#pragma unroll
            for (int ni = 0; ni < 8; ++ni) {
                uint32_t bh[2], bl[2];
                LDSM2(bh, bKh + ni * (8 * 272) + koff);
                LDSM2(bl, bKl + ni * (8 * 272) + koff);
                MMA16816(sc[ni], ah, bh);
                MMA16816(sc[ni], ah, bl);
                MMA16816(sc[ni], al, bh);
            }
        }

#pragma unroll
        for (int ni = 0; ni < 8; ++ni)
#pragma unroll
            for (int j = 0; j < 4; ++j) sc[ni][j] *= SCALE_;

        if (t == qt) {   // diagonal tile
            const int qr0 = q0 + wrow + (lane >> 2);
#pragma unroll
            for (int ni = 0; ni < 8; ++ni) {
                const int kc = k0 + ni * 8 + (lane & 3) * 2;
                if (kc > qr0)         sc[ni][0] = -1e30f;
                if (kc + 1 > qr0)     sc[ni][1] = -1e30f;
                if (kc > qr0 + 8)     sc[ni][2] = -1e30f;
                if (kc + 1 > qr0 + 8) sc[ni][3] = -1e30f;
            }
        }

        // ---- online softmax ----
        float mx0 = -1e30f, mx1 = -1e30f;
#pragma unroll
        for (int ni = 0; ni < 8; ++ni) {
            mx0 = fmaxf(mx0, fmaxf(sc[ni][0], sc[ni][1]));
            mx1 = fmaxf(mx1, fmaxf(sc[ni][2], sc[ni][3]));
        }
        mx0 = fmaxf(mx0, __shfl_xor_sync(0xffffffffu, mx0, 1));
        mx0 = fmaxf(mx0, __shfl_xor_sync(0xffffffffu, mx0, 2));
        mx1 = fmaxf(mx1, __shfl_xor_sync(0xffffffffu, mx1, 1));
        mx1 = fmaxf(mx1, __shfl_xor_sync(0xffffffffu, mx1, 2));

        const float nm0 = fmaxf(m0, mx0), nm1 = fmaxf(m1, mx1);
        const float al0 = __expf(m0 - nm0), al1 = __expf(m1 - nm1);
        float s0 = 0.f, s1 = 0.f;
#pragma unroll
        for (int ni = 0; ni < 8; ++ni) {
            sc[ni][0] = __expf(sc[ni][0] - nm0); s0 += sc[ni][0];
            sc[ni][1] = __expf(sc[ni][1] - nm0); s0 += sc[ni][1];
            sc[ni][2] = __expf(sc[ni][2] - nm1); s1 += sc[ni][2];
            sc[ni][3] = __expf(sc[ni][3] - nm1); s1 += sc[ni][3];
        }
        s0 += __shfl_xor_sync(0xffffffffu, s0, 1);
        s0 += __shfl_xor_sync(0xffffffffu, s0, 2);
        s1 += __shfl_xor_sync(0xffffffffu, s1, 1);
        s1 += __shfl_xor_sync(0xffffffffu, s1, 2);
        l0 = l0 * al0 + s0; l1 = l1 * al1 + s1;
        m0 = nm0; m1 = nm1;

#pragma unroll
        for (int i = 0; i < 16; ++i) {
            ao[i][0] *= al0; ao[i][1] *= al0;
            ao[i][2] *= al1; ao[i][3] *= al1;
        }

        // ---- O += P @ V (3-product split, validated R7 math) ----
#pragma unroll
        for (int ks = 0; ks < 4; ++ks) {
            const float p0 = sc[2 * ks][0], p1 = sc[2 * ks][1];
            const float p2 = sc[2 * ks][2], p3 = sc[2 * ks][3];
            const float p4 = sc[2 * ks + 1][0], p5 = sc[2 * ks + 1][1];
            const float p6 = sc[2 * ks + 1][2], p7 = sc[2 * ks + 1][3];
            const __nv_bfloat16 q0b = __float2bfloat16_rn(p0), q1b = __float2bfloat16_rn(p1);
            const __nv_bfloat16 q2b = __float2bfloat16_rn(p2), q3b = __float2bfloat16_rn(p3);
            const __nv_bfloat16 q4b = __float2bfloat16_rn(p4), q5b = __float2bfloat16_rn(p5);
            const __nv_bfloat16 q6b = __float2bfloat16_rn(p6), q7b = __float2bfloat16_rn(p7);
            uint32_t pah[4], pal[4];
            pah[0] = packbf2(q0b, q1b);
            pah[1] = packbf2(q2b, q3b);
            pah[2] = packbf2(q4b, q5b);
            pah[3] = packbf2(q6b, q7b);
            pal[0] = packbf2(__float2bfloat16_rn(p0 - __bfloat162float(q0b)),
                             __float2bfloat16_rn(p1 - __bfloat162float(q1b)));
            pal[1] = packbf2(__float2bfloat16_rn(p2 - __bfloat162float(q2b)),
                             __float2bfloat16_rn(p3 - __bfloat162float(q3b)));
            pal[2] = packbf2(__float2bfloat16_rn(p4 - __bfloat162float(q4b)),
                             __float2bfloat16_rn(p5 - __bfloat162float(q5b)));
            pal[3] = packbf2(__float2bfloat16_rn(p6 - __bfloat162float(q6b)),
                             __float2bfloat16_rn(p7 - __bfloat162float(q7b)));

            const uint32_t koff = ks * 32;
#pragma unroll
            for (int ni = 0; ni < 16; ++ni) {
                uint32_t bh[2], bl[2];
                LDSM2(bh, bVh + ni * (8 * 144) + koff);
                LDSM2(bl, bVl + ni * (8 * 144) + koff);
                MMA16816(ao[ni], pah, bh);
                MMA16816(ao[ni], pal, bh);
                MMA16816(ao[ni], pah, bl);
            }
        }
        __syncthreads();   // compute done before buffer restaged
    }

    // ---- epilogue ----
    const float inv0 = 1.0f / l0, inv1 = 1.0f / l1;
    const int r0 = q0 + wrow + (lane >> 2);
    const int ecol = (lane & 3) * 2;
    float* Ob0 = O + ((size_t)(b * L_ + r0) * NH_ + h) * HD_ + ecol;
    float* Ob1 = O + ((size_t)(b * L_ + r0 + 8) * NH_ + h) * HD_ + ecol;
#pragma unroll
    for (int ni = 0; ni < 16; ++ni) {
        *(float2*)(Ob0 + ni * 8) = make_float2(ao[ni][0] * inv0, ao[ni][1] * inv0);
        *(float2*)(Ob1 + ni * 8) = make_float2(ao[ni][2] * inv1, ao[ni][3] * inv1);
    }
}

// ---------------------------------------------------------------------------
extern "C" void kernel_launch(void* const* d_in, const int* in_sizes, int n_in,
                              void* d_out, int out_size) {
    const float* x  = (const float*)d_in[0];
    const float* Wq = (const float*)d_in[1];
    const float* Wk = (const float*)d_in[2];
    const float* Wv = (const float*)d_in[3];
    const float* Wo = (const float*)d_in[4];
    float* out = (float*)d_out;

    float *q, *k, *v, *o;
    cudaGetSymbolAddress((void**)&q, g_q);
    cudaGetSymbolAddress((void**)&k, g_k);
    cudaGetSymbolAddress((void**)&v, g_v);
    cudaGetSymbolAddress((void**)&o, g_o);
    __nv_bfloat16 *xh, *xl, *wqh, *wql, *wkh, *wkl, *wvh, *wvl, *woh, *wol, *oh, *ol;
    __nv_bfloat16 *qh, *ql, *kh, *kl, *vth, *vtl;
    cudaGetSymbolAddress((void**)&xh, g_xh);   cudaGetSymbolAddress((void**)&xl, g_xl);
    cudaGetSymbolAddress((void**)&wqh, g_wqh); cudaGetSymbolAddress((void**)&wql, g_wql);
    cudaGetSymbolAddress((void**)&wkh, g_wkh); cudaGetSymbolAddress((void**)&wkl, g_wkl);
    cudaGetSymbolAddress((void**)&wvh, g_wvh); cudaGetSymbolAddress((void**)&wvl, g_wvl);
    cudaGetSymbolAddress((void**)&woh, g_woh); cudaGetSymbolAddress((void**)&wol, g_wol);
    cudaGetSymbolAddress((void**)&oh, g_oh);   cudaGetSymbolAddress((void**)&ol, g_ol);
    cudaGetSymbolAddress((void**)&qh, g_qh);   cudaGetSymbolAddress((void**)&ql, g_ql);
    cudaGetSymbolAddress((void**)&kh, g_kh);   cudaGetSymbolAddress((void**)&kl, g_kl);
    cudaGetSymbolAddress((void**)&vth, g_vth); cudaGetSymbolAddress((void**)&vtl, g_vtl);

    const int M = B_ * L_;       // 4096
    const int NKVD = NKV_ * HD_; // 1024

    cudaFuncSetAttribute(gemm_mma, cudaFuncAttributeMaxDynamicSharedMemorySize, GT_SMEM);
    cudaFuncSetAttribute(flash_mma, cudaFuncAttributeMaxDynamicSharedMemorySize, FM_SMEM);

    rope_table_kernel<<<(L_ * 64 + 255) / 256, 256>>>();

    split_bf16<<<(M * D_ / 4 + 255) / 256, 256>>>(x, xh, xl, M * D_ / 4);
    split_bf16<<<(D_ * D_ / 4 + 255) / 256, 256>>>(Wq, wqh, wql, D_ * D_ / 4);
    split_bf16<<<(NKVD * D_ / 4 + 255) / 256, 256>>>(Wk, wkh, wkl, NKVD * D_ / 4);
    split_bf16<<<(NKVD * D_ / 4 + 255) / 256, 256>>>(Wv, wvh, wvl, NKVD * D_ / 4);
    split_bf16<<<(D_ * D_ / 4 + 255) / 256, 256>>>(Wo, woh, wol, D_ * D_ / 4);

    gemm_mma<<<dim3(D_ / 128, M / 128), 256, GT_SMEM>>>(xh, xl, wqh, wql, q, D_, D_);
    gemm_mma<<<dim3(NKVD / 128, M / 128), 256, GT_SMEM>>>(xh, xl, wkh, wkl, k, NKVD, D_);
    gemm_mma<<<dim3(NKVD / 128, M / 128), 256, GT_SMEM>>>(xh, xl, wvh, wvl, v, NKVD, D_);

    {
        const long long total = (long long)B_ * L_ * (NH_ + NKV_) * 64;
        const int blocks = (int)((total + 255) / 256);
        rope_split_kernel<<<blocks, 256>>>(q, k, qh, ql, kh, kl);
    }
    vt_split_kernel<<<dim3(L_ / 32, HD_ / 32, B_ * NKV_), dim3(32, 8)>>>(v, vth, vtl);

    flash_mma<<<dim3(L_ / 64, NH_, B_), 128, FM_SMEM>>>(qh, ql, kh, kl, vth, vtl, o);

    split_bf16<<<(M * D_ / 4 + 255) / 256, 256>>>(o, oh, ol, M * D_ / 4);
    gemm_mma<<<dim3(D_ / 128, M / 128), 256, GT_SMEM>>>(oh, ol, woh, wol, out, D_, D_);
}